// round 12
// baseline (speedup 1.0000x reference)
#include <cuda_runtime.h>
#include <cuda_bf16.h>
#include <cuda_fp16.h>
#include <mma.h>
#include <math.h>
#include <stdint.h>

using namespace nvcuda;

#define SRC 50
#define TRGN 50
#define BSZ 32
#define EMBED 620
#define ECH 1000
#define DCH 1000
#define VOCAB 30000
#define NSTEP 49
#define MROWS (NSTEP*BSZ)          /* 1568 */
#define KP_WP 3648
#define KP_CTX 2048
#define KP_H 1024
#define KP_EMB 640
#define NGH 4000
#define RGRID 64
#define LROWS 1664
#define LCOLS 30208

// ============================ static scratch (bss, zero-initialized) ============================
__device__ __half d_Wp16H[(size_t)VOCAB*KP_WP], d_Wp16L[(size_t)VOCAB*KP_WP];  // W_p fp16 hi/lo
__device__ __half d_C2[(size_t)MROWS*KP_WP];                                    // comb2, single fp16
__device__ __nv_bfloat16 d_annSH[(size_t)SRC*BSZ*KP_CTX], d_annSL[(size_t)SRC*BSZ*KP_CTX];
__device__ __nv_bfloat16 d_WhcH[(size_t)NGH*KP_H], d_WhcL[(size_t)NGH*KP_H];
__device__ __nv_bfloat16 d_Wc2H[(size_t)DCH*KP_CTX], d_Wc2L[(size_t)DCH*KP_CTX];
__device__ __nv_bfloat16 d_Wih1H[(size_t)3*DCH*KP_EMB], d_Wih1L[(size_t)3*DCH*KP_EMB];
__device__ __nv_bfloat16 d_Wih2H[(size_t)3*DCH*KP_CTX], d_Wih2L[(size_t)3*DCH*KP_CTX];
__device__ __nv_bfloat16 d_WhH[DCH*KP_H], d_WhL[DCH*KP_H];
__device__ __nv_bfloat16 d_EmbH[(size_t)MROWS*KP_EMB], d_EmbL[(size_t)MROWS*KP_EMB];
__device__ __nv_bfloat16 d_a0H[BSZ*KP_H], d_a0L[BSZ*KP_H];
__device__ __nv_bfloat16 d_hsH[2][BSZ*KP_H], d_hsL[2][BSZ*KP_H];
__device__ float d_annProj[SRC*BSZ*DCH];
__device__ float d_annIh[(size_t)SRC*BSZ*3*DCH];
__device__ float d_hbuf[2][BSZ*DCH];
__device__ float d_ghp[BSZ*NGH];
__device__ float d_attnS[SRC*BSZ];
__device__ float d_giEmb[(size_t)MROWS*3*DCH];
__device__ float d_bcomb[NGH];
__device__ float d_logits[(size_t)LROWS*LCOLS];

__device__ int g_cnt;
__device__ volatile int g_gen;

// ============================ helpers ============================
__device__ __forceinline__ uint32_t smem_u32(const void* p) {
    uint32_t a;
    asm("{ .reg .u64 t; cvta.to.shared.u64 t, %1; cvt.u32.u64 %0, t; }" : "=r"(a) : "l"(p));
    return a;
}
__device__ __forceinline__ void cp_async16(uint32_t dst, const void* src) {
    asm volatile("cp.async.cg.shared.global [%0], [%1], 16;\n" :: "r"(dst), "l"(src));
}
__device__ __forceinline__ void cp_commit() {
    asm volatile("cp.async.commit_group;\n" ::: "memory");
}
__device__ __forceinline__ void gridbar() {
    __syncthreads();
    if (threadIdx.x == 0) {
        __threadfence();
        int gen = g_gen;
        if (atomicAdd(&g_cnt, 1) == RGRID - 1) {
            g_cnt = 0;
            __threadfence();
            g_gen = gen + 1;
        } else {
            while (g_gen == gen) { __nanosleep(64); }
        }
        __threadfence();
    }
    __syncthreads();
}

// ============================ BIG GEMM: fp16 2-product, 128x256 tile, K-chunk 64, 2-stage, 2 CTA/SM ============================
// logits = C2 @ (Wp16H + Wp16L)^T
#define BLDT 72
#define BSTAGE ((128 + 256) * BLDT)
#define SMEM_BIG (2 * BSTAGE * 2)     /* 110592 B -> 2 CTAs/SM */

__global__ __launch_bounds__(256, 2) void k_wgemmBig()
{
    extern __shared__ __half tiles[];
    const int tid = threadIdx.x, wid = tid >> 5;
    const int m0 = blockIdx.x * 128, n0 = blockIdx.y * 256;
    const int wm = wid & 1, wn = wid >> 1;
    const int wmo = wm * 64, wno = wn * 64;

    wmma::fragment<wmma::accumulator, 16, 16, 16, float> acc[4][4];
#pragma unroll
    for (int i = 0; i < 4; i++)
#pragma unroll
        for (int j = 0; j < 4; j++) wmma::fill_fragment(acc[i][j], 0.0f);

    const int cpp = KP_WP >> 6;        // 57
    const int total = 2 * cpp;         // 114: products C2*WpH, C2*WpL

    auto prefetch = [&](int c, int stage) {
        int p = c / cpp;
        int kc = (c - p * cpp) << 6;
        const __half* Bp = (p == 0) ? d_Wp16H : d_Wp16L;
        __half* As = tiles + stage * BSTAGE;
        __half* Bs = As + 128 * BLDT;
#pragma unroll
        for (int q = 0; q < 4; q++) {          // A: 128 rows x 8 segs
            int it = tid + q * 256;
            int r = it >> 3, s = it & 7;
            int gm = m0 + r; if (gm >= MROWS) gm = MROWS - 1;
            cp_async16(smem_u32(As + r * BLDT + s * 8), d_C2 + (size_t)gm * KP_WP + kc + s * 8);
        }
#pragma unroll
        for (int q = 0; q < 8; q++) {          // B: 256 rows x 8 segs
            int it = tid + q * 256;
            int r = it >> 3, s = it & 7;
            int gn = n0 + r; if (gn >= VOCAB) gn = VOCAB - 1;
            cp_async16(smem_u32(Bs + r * BLDT + s * 8), Bp + (size_t)gn * KP_WP + kc + s * 8);
        }
        cp_commit();
    };

    prefetch(0, 0);
    prefetch(1, 1);

    for (int c = 0; c < total; c++) {
        if (c + 1 < total) { asm volatile("cp.async.wait_group 1;\n" ::: "memory"); }
        else               { asm volatile("cp.async.wait_group 0;\n" ::: "memory"); }
        __syncthreads();
        const __half* As = tiles + (c & 1) * BSTAGE;
        const __half* Bs = As + 128 * BLDT;
#pragma unroll
        for (int kk = 0; kk < 64; kk += 16) {
            wmma::fragment<wmma::matrix_a, 16,16,16, __half, wmma::row_major> af[4];
            wmma::fragment<wmma::matrix_b, 16,16,16, __half, wmma::col_major> bf[4];
#pragma unroll
            for (int i = 0; i < 4; i++)
                wmma::load_matrix_sync(af[i], As + (wmo + i * 16) * BLDT + kk, BLDT);
#pragma unroll
            for (int j = 0; j < 4; j++)
                wmma::load_matrix_sync(bf[j], Bs + (wno + j * 16) * BLDT + kk, BLDT);
#pragma unroll
            for (int i = 0; i < 4; i++)
#pragma unroll
                for (int j = 0; j < 4; j++)
                    wmma::mma_sync(acc[i][j], af[i], bf[j], acc[i][j]);
        }
        __syncthreads();
        if (c + 2 < total) prefetch(c + 2, c & 1);
    }

#pragma unroll
    for (int i = 0; i < 4; i++)
#pragma unroll
        for (int j = 0; j < 4; j++)
            wmma::store_matrix_sync(d_logits + (size_t)(m0 + wmo + i * 16) * LCOLS + n0 + wno + j * 16,
                                    acc[i][j], LCOLS, wmma::mem_row_major);
}

// ============================ generic WMMA bf16 split GEMM (2-stage, LDT 40) ============================
template<int BM>
__global__ __launch_bounds__(256) void k_wgemm(
    const __nv_bfloat16* __restrict__ Ah, const __nv_bfloat16* __restrict__ Al, int lda,
    const __nv_bfloat16* __restrict__ Bh, const __nv_bfloat16* __restrict__ Bl, int ldb,
    const float* __restrict__ bias,
    const float* __restrict__ Dadd, int ldd,
    float* __restrict__ C, int ldc,
    int M, int N, int KP, int act)
{
    constexpr int MFR = (BM == 128) ? 2 : 1;
    constexpr int NFR = (BM == 128) ? 4 : 2;
    constexpr int AITEMS = BM * 4;
    constexpr int LDT = 40;
    constexpr int LDC_S = 136;
    constexpr int STAGE = (BM + 128) * LDT;

    extern __shared__ char smem[];
    __nv_bfloat16* tiles = (__nv_bfloat16*)smem;
    float* Cs = (float*)smem;

    const int tid = threadIdx.x, wid = tid >> 5;
    const int m0 = blockIdx.x * BM, n0 = blockIdx.y * 128;

    int wm, wn;
    if (BM == 128) { wm = wid & 3; wn = wid >> 2; }
    else           { wm = wid & 1; wn = wid >> 1; }
    const int wrow = wm * (16 * MFR);
    const int wcol = wn * (16 * NFR);

    wmma::fragment<wmma::accumulator, 16, 16, 16, float> acc[MFR][NFR];
#pragma unroll
    for (int i = 0; i < MFR; i++)
#pragma unroll
        for (int j = 0; j < NFR; j++)
            wmma::fill_fragment(acc[i][j], 0.0f);

    const int cpp = KP >> 5;
    const int total = 3 * cpp;

    auto prefetch = [&](int c, int stage) {
        int p = c / cpp;
        int kc = (c - p * cpp) << 5;
        const __nv_bfloat16* Ap = (p < 2) ? Ah : Al;
        const __nv_bfloat16* Bp = (p == 1) ? Bl : Bh;
        __nv_bfloat16* As = tiles + stage * STAGE;
        __nv_bfloat16* Bs = As + BM * LDT;
#pragma unroll
        for (int q = 0; q < (BM == 128 ? 2 : 1); q++) {
            int it = tid + q * 256;
            if (BM == 32 && it >= AITEMS) break;
            int r = it >> 2, seg = it & 3;
            int gm = m0 + r; if (gm >= M) gm = M - 1;
            cp_async16(smem_u32(As + r * LDT + seg * 8), Ap + (size_t)gm * lda + kc + seg * 8);
        }
#pragma unroll
        for (int q = 0; q < 2; q++) {
            int it = tid + q * 256;
            int r = it >> 2, seg = it & 3;
            int gn = n0 + r; if (gn >= N) gn = N - 1;
            cp_async16(smem_u32(Bs + r * LDT + seg * 8), Bp + (size_t)gn * ldb + kc + seg * 8);
        }
        cp_commit();
    };

    prefetch(0, 0);
    prefetch(1, 1);

    for (int c = 0; c < total; c++) {
        if (c + 1 < total) { asm volatile("cp.async.wait_group 1;\n" ::: "memory"); }
        else               { asm volatile("cp.async.wait_group 0;\n" ::: "memory"); }
        __syncthreads();
        const __nv_bfloat16* As = tiles + (c & 1) * STAGE;
        const __nv_bfloat16* Bs = As + BM * LDT;
#pragma unroll
        for (int kk = 0; kk < 32; kk += 16) {
            wmma::fragment<wmma::matrix_a, 16,16,16, __nv_bfloat16, wmma::row_major> af[MFR];
            wmma::fragment<wmma::matrix_b, 16,16,16, __nv_bfloat16, wmma::col_major> bf[NFR];
#pragma unroll
            for (int i = 0; i < MFR; i++)
                wmma::load_matrix_sync(af[i], As + (wrow + i * 16) * LDT + kk, LDT);
#pragma unroll
            for (int j = 0; j < NFR; j++)
                wmma::load_matrix_sync(bf[j], Bs + (wcol + j * 16) * LDT + kk, LDT);
#pragma unroll
            for (int i = 0; i < MFR; i++)
#pragma unroll
                for (int j = 0; j < NFR; j++)
                    wmma::mma_sync(acc[i][j], af[i], bf[j], acc[i][j]);
        }
        __syncthreads();
        if (c + 2 < total) prefetch(c + 2, c & 1);
    }

#pragma unroll
    for (int i = 0; i < MFR; i++)
#pragma unroll
        for (int j = 0; j < NFR; j++)
            wmma::store_matrix_sync(Cs + (wrow + i * 16) * LDC_S + wcol + j * 16,
                                    acc[i][j], LDC_S, wmma::mem_row_major);
    __syncthreads();
    for (int idx = tid; idx < BM * 128; idx += 256) {
        int r = idx >> 7, cc = idx & 127;
        int gm = m0 + r, gn = n0 + cc;
        if (gm < M && gn < N) {
            float v = Cs[r * LDC_S + cc];
            if (bias) v += bias[gn];
            if (Dadd) v += Dadd[(size_t)gm * ldd + gn];
            if (act)  v = tanhf(v);
            C[(size_t)gm * ldc + gn] = v;
        }
    }
}

// ============================ persistent recurrence kernel ============================
__global__ __launch_bounds__(256) void k_recur(const float* __restrict__ ann,
                                               const float* __restrict__ w_a,
                                               float* __restrict__ attns,
                                               float* __restrict__ hidden)
{
    __shared__ char smr[40192];
    const int bid = blockIdx.x;
    const int tid = threadIdx.x;
    const int wid = tid >> 5;

    __nv_bfloat16* Ath = (__nv_bfloat16*)smr;
    __nv_bfloat16* Atl = Ath + 2 * 32 * 40;
    __nv_bfloat16* Bth = Atl + 2 * 32 * 40;
    __nv_bfloat16* Btl = Bth + 2 * 64 * 40;
    float* Cs = (float*)(Btl + 2 * 64 * 40);
    float* sc  = (float*)smr;
    float* sat = (float*)smr;
    float* sgi = sat + 64;

    for (int step = 0; step < NSTEP; step++) {
        const int cur = step & 1;
        // ---- phase A: ghp = h @ [W_hh; W_c1]^T + bcomb (cp.async 2-stage) ----
        if (bid < 63) {
            const int n0 = bid * 64;
            const int wm = wid & 1, wn = wid >> 1;
            const __nv_bfloat16* hH = d_hsH[cur];
            const __nv_bfloat16* hL = d_hsL[cur];

            auto prefA = [&](int c, int st) {
                const int kc = c << 5;
                {
                    int it = tid & 127;
                    int r = it >> 2, seg = it & 3;
                    const __nv_bfloat16* src = (tid < 128) ? hH : hL;
                    __nv_bfloat16* dst = ((tid < 128) ? Ath : Atl) + st * (32 * 40);
                    cp_async16(smem_u32(dst + r * 40 + seg * 8),
                               src + (size_t)r * KP_H + kc + seg * 8);
                }
#pragma unroll
                for (int q = 0; q < 2; q++) {
                    int it = tid + q * 256;
                    int r = (it & 255) >> 2, seg = it & 3;
                    int gn = n0 + r; if (gn >= NGH) gn = NGH - 1;
                    const __nv_bfloat16* src = (it < 256) ? d_WhcH : d_WhcL;
                    __nv_bfloat16* dst = ((it < 256) ? Bth : Btl) + st * (64 * 40);
                    cp_async16(smem_u32(dst + r * 40 + seg * 8),
                               src + (size_t)gn * KP_H + kc + seg * 8);
                }
                cp_commit();
            };

            wmma::fragment<wmma::accumulator, 16, 16, 16, float> acc;
            wmma::fill_fragment(acc, 0.0f);
            prefA(0, 0);
            prefA(1, 1);
#pragma unroll 1
            for (int c = 0; c < 32; c++) {
                const int st = c & 1;
                if (c + 1 < 32) { asm volatile("cp.async.wait_group 1;\n" ::: "memory"); }
                else            { asm volatile("cp.async.wait_group 0;\n" ::: "memory"); }
                __syncthreads();
#pragma unroll
                for (int kk = 0; kk < 32; kk += 16) {
                    wmma::fragment<wmma::matrix_a, 16,16,16, __nv_bfloat16, wmma::row_major> ah, al;
                    wmma::fragment<wmma::matrix_b, 16,16,16, __nv_bfloat16, wmma::col_major> bh, bl;
                    wmma::load_matrix_sync(ah, Ath + st * (32*40) + (wm * 16) * 40 + kk, 40);
                    wmma::load_matrix_sync(al, Atl + st * (32*40) + (wm * 16) * 40 + kk, 40);
                    wmma::load_matrix_sync(bh, Bth + st * (64*40) + (wn * 16) * 40 + kk, 40);
                    wmma::load_matrix_sync(bl, Btl + st * (64*40) + (wn * 16) * 40 + kk, 40);
                    wmma::mma_sync(acc, ah, bh, acc);
                    wmma::mma_sync(acc, ah, bl, acc);
                    wmma::mma_sync(acc, al, bh, acc);
                }
                __syncthreads();
                if (c + 2 < 32) prefA(c + 2, st);
            }
            wmma::store_matrix_sync(Cs + (wm * 16) * 72 + wn * 16, acc, 72, wmma::mem_row_major);
            __syncthreads();
            for (int idx = tid; idx < 32 * 64; idx += 256) {
                int r = idx >> 6, cc = idx & 63;
                int gn = n0 + cc;
                if (gn < NGH)
                    d_ghp[r * NGH + gn] = Cs[r * 72 + cc] + d_bcomb[gn];
            }
        }
        gridbar();

        // ---- phase B: attention + softmax over batch ----
        if (bid < SRC) {
            const int s = bid;
            int b = tid >> 3, jt = tid & 7;
            const float* hp = d_ghp + b * NGH + 3 * DCH;
            const float* ap = d_annProj + (size_t)(s * BSZ + b) * DCH;
            float acc = 0.f;
            for (int j = jt; j < DCH; j += 8)
                acc += tanhf(hp[j] + ap[j]) * w_a[j];
            for (int off = 4; off; off >>= 1)
                acc += __shfl_down_sync(0xffffffffu, acc, off, 8);
            if (jt == 0) sc[b] = acc;
            __syncthreads();
            if (tid < 32) {
                float v = sc[tid];
                float m = v;
                for (int off = 16; off; off >>= 1) m = fmaxf(m, __shfl_xor_sync(0xffffffffu, m, off));
                float e = expf(v - m);
                float ssum = e;
                for (int off = 16; off; off >>= 1) ssum += __shfl_xor_sync(0xffffffffu, ssum, off);
                float a = e / ssum;
                d_attnS[s * BSZ + tid] = a;
                attns[(size_t)(step + 1) * SRC * BSZ + s * BSZ + tid] = a;
            }
        }
        gridbar();

        // ---- phase C: context + gi + GRU gates ----
        if (bid < BSZ) {
            const int b = bid;
            if (tid < SRC) sat[tid] = d_attnS[tid * BSZ + b];
            __syncthreads();
            for (int e = tid; e < 2 * ECH; e += 256) {
                float acc = 0.f;
                const float* ap = ann + (size_t)b * (2 * ECH) + e;
#pragma unroll 10
                for (int s = 0; s < SRC; s++)
                    acc += sat[s] * ap[(size_t)s * BSZ * (2 * ECH)];
                d_C2[(size_t)(step * BSZ + b) * KP_WP + EMBED + DCH + e] = __float2half(acc);
            }
            const float* gE = d_giEmb + ((size_t)step * BSZ + b) * 3 * DCH;
            for (int j = tid; j < 3 * DCH; j += 256) {
                float acc = gE[j];
                const float* ip = d_annIh + (size_t)b * 3 * DCH + j;
#pragma unroll 10
                for (int s = 0; s < SRC; s++)
                    acc += sat[s] * ip[(size_t)s * BSZ * 3 * DCH];
                sgi[j] = acc;
            }
            __syncthreads();
            const float* gh = d_ghp + b * NGH;
            for (int j = tid; j < DCH; j += 256) {
                float r = 1.f / (1.f + expf(-(sgi[j] + gh[j])));
                float z = 1.f / (1.f + expf(-(sgi[DCH + j] + gh[DCH + j])));
                float n = tanhf(sgi[2 * DCH + j] + r * gh[2 * DCH + j]);
                float hp = d_hbuf[cur][b * DCH + j];
                float hn = (1.f - z) * n + z * hp;
                d_hbuf[cur ^ 1][b * DCH + j] = hn;
                __nv_bfloat16 hh = __float2bfloat16(hn);
                d_hsH[cur ^ 1][b * KP_H + j] = hh;
                d_hsL[cur ^ 1][b * KP_H + j] = __float2bfloat16(hn - __bfloat162float(hh));
                d_C2[(size_t)(step * BSZ + b) * KP_WP + EMBED + j] = __float2half(hp);
                if (step == NSTEP - 1) hidden[b * DCH + j] = hn;
            }
        }
        gridbar();
    }
}

// ============================ small kernels ============================
__global__ void k_split8(const float* __restrict__ src, int sld, int colOff, int rows, int cols,
                         __nv_bfloat16* __restrict__ hi, __nv_bfloat16* __restrict__ lo, int dld)
{
    int i8 = blockIdx.x * blockDim.x + threadIdx.x;
    int total8 = (rows * dld) >> 3;
    if (i8 >= total8) return;
    int i = i8 << 3;
    int r = i / dld, c = i - r * dld;
    float x[8];
    if (c + 7 < cols) {
        const float* p = src + (size_t)r * sld + colOff + c;
        *(float4*)(x)     = *(const float4*)(p);
        *(float4*)(x + 4) = *(const float4*)(p + 4);
    } else {
#pragma unroll
        for (int q = 0; q < 8; q++)
            x[q] = (c + q < cols) ? src[(size_t)r * sld + colOff + c + q] : 0.f;
    }
    __nv_bfloat16 h[8], l[8];
#pragma unroll
    for (int q = 0; q < 8; q++) {
        h[q] = __float2bfloat16(x[q]);
        l[q] = __float2bfloat16(x[q] - __bfloat162float(h[q]));
    }
    *(uint4*)(hi + i) = *(uint4*)h;
    *(uint4*)(lo + i) = *(uint4*)l;
}

// fp16 hi/lo split, 8 elems/thread (W_p)
__global__ void k_splitH8(const float* __restrict__ src, int sld, int colOff, int rows, int cols,
                          __half* __restrict__ hi, __half* __restrict__ lo, int dld)
{
    int i8 = blockIdx.x * blockDim.x + threadIdx.x;
    int total8 = (rows * dld) >> 3;
    if (i8 >= total8) return;
    int i = i8 << 3;
    int r = i / dld, c = i - r * dld;
    float x[8];
    if (c + 7 < cols) {
        const float* p = src + (size_t)r * sld + colOff + c;
        *(float4*)(x)     = *(const float4*)(p);
        *(float4*)(x + 4) = *(const float4*)(p + 4);
    } else {
#pragma unroll
        for (int q = 0; q < 8; q++)
            x[q] = (c + q < cols) ? src[(size_t)r * sld + colOff + c + q] : 0.f;
    }
    __half h[8], l[8];
#pragma unroll
    for (int q = 0; q < 8; q++) {
        h[q] = __float2half(x[q]);
        l[q] = __float2half(x[q] - __half2float(h[q]));
    }
    *(uint4*)(hi + i) = *(uint4*)h;
    *(uint4*)(lo + i) = *(uint4*)l;
}

__global__ void k_zero(float* __restrict__ preds0, float* __restrict__ attns0, int n)
{
    int i = blockIdx.x * blockDim.x + threadIdx.x;
    if (i < n) preds0[i] = 0.f;
    if (i < SRC * BSZ) attns0[i] = 0.f;
}

__global__ void k_bcomb(const float* __restrict__ b_hh)
{
    int i = blockIdx.x * blockDim.x + threadIdx.x;
    if (i < NGH) d_bcomb[i] = (i < 3 * DCH) ? b_hh[i] : 0.f;
}

__global__ void k_embedS(const int* __restrict__ tok, const float* __restrict__ emb)
{
    int i = blockIdx.x * blockDim.x + threadIdx.x;
    if (i >= MROWS * KP_EMB) return;
    int m = i / KP_EMB, e = i - m * KP_EMB;
    float x = (e < EMBED) ? emb[(size_t)tok[m] * EMBED + e] : 0.f;
    __nv_bfloat16 h = __float2bfloat16(x);
    d_EmbH[i] = h;
    d_EmbL[i] = __float2bfloat16(x - __bfloat162float(h));
    if (e < EMBED)
        d_C2[(size_t)m * KP_WP + e] = __float2half(x);
}

__global__ __launch_bounds__(256) void k_lsm(const float* __restrict__ bias, float* __restrict__ preds)
{
    int m = blockIdx.x;
    const float* row = d_logits + (size_t)m * LCOLS;
    float* outr = preds + (size_t)(m + BSZ) * VOCAB;
    int t = threadIdx.x;
    __shared__ float rm[256], rs[256];
    float mx = -1e30f, sum = 0.f;
    for (int v = t; v < VOCAB; v += 256) {
        float x = row[v] + bias[v];
        if (x > mx) { sum = sum * expf(mx - x) + 1.f; mx = x; }
        else sum += expf(x - mx);
    }
    rm[t] = mx; rs[t] = sum; __syncthreads();
    for (int s2 = 128; s2; s2 >>= 1) {
        if (t < s2) {
            float m1 = rm[t], m2 = rm[t + s2];
            float M = fmaxf(m1, m2);
            rs[t] = rs[t] * expf(m1 - M) + rs[t + s2] * expf(m2 - M);
            rm[t] = M;
        }
        __syncthreads();
    }
    float lse = rm[0] + logf(rs[0]);
    for (int v = t; v < VOCAB; v += 256)
        outr[v] = row[v] + bias[v] - lse;
}

// ============================ host ============================
#define SYM(p, s) do { void* _t; cudaGetSymbolAddress(&_t, s); p = (decltype(p))_t; } while (0)

#define SMEM_G128 (128 * 136 * 4)
#define SMEM_G32  (2 * (32 + 128) * 40 * 2 + 1024)

static inline void g128(const __nv_bfloat16* Ah, const __nv_bfloat16* Al, int lda,
                        const __nv_bfloat16* Bh, const __nv_bfloat16* Bl, int ldb,
                        const float* bias, const float* Dadd, int ldd,
                        float* C, int ldc, int M, int N, int KP, int act)
{
    dim3 g((M + 127) / 128, (N + 127) / 128);
    k_wgemm<128><<<g, 256, SMEM_G128>>>(Ah, Al, lda, Bh, Bl, ldb, bias, Dadd, ldd, C, ldc, M, N, KP, act);
}
static inline void g32(const __nv_bfloat16* Ah, const __nv_bfloat16* Al, int lda,
                       const __nv_bfloat16* Bh, const __nv_bfloat16* Bl, int ldb,
                       const float* bias, const float* Dadd, int ldd,
                       float* C, int ldc, int M, int N, int KP, int act)
{
    dim3 g((M + 31) / 32, (N + 127) / 128);
    k_wgemm<32><<<g, 256, SMEM_G32>>>(Ah, Al, lda, Bh, Bl, ldb, bias, Dadd, ldd, C, ldc, M, N, KP, act);
}

extern "C" void kernel_launch(void* const* d_in, const int* in_sizes, int n_in,
                              void* d_out, int out_size)
{
    (void)in_sizes; (void)n_in; (void)out_size;
    const int*   tok  = (const int*)  d_in[0];
    const float* ann  = (const float*)d_in[1];
    const float* emb  = (const float*)d_in[2];
    const float* W_h  = (const float*)d_in[3];
    const float* b_h  = (const float*)d_in[4];
    const float* W_c  = (const float*)d_in[5];
    const float* b_c  = (const float*)d_in[6];
    const float* w_a  = (const float*)d_in[7];
    const float* W_ih = (const float*)d_in[8];
    const float* W_hh = (const float*)d_in[9];
    const float* b_ih = (const float*)d_in[10];
    const float* b_hh = (const float*)d_in[11];
    const float* W_p  = (const float*)d_in[12];
    const float* b_p  = (const float*)d_in[13];

    float* out    = (float*)d_out;
    float* preds  = out;
    float* hidden = out + (size_t)TRGN * BSZ * VOCAB;
    float* attns  = hidden + BSZ * DCH;

    static bool attrDone = false;
    if (!attrDone) {
        cudaFuncSetAttribute(k_wgemm<128>, cudaFuncAttributeMaxDynamicSharedMemorySize, SMEM_G128);
        cudaFuncSetAttribute(k_wgemm<32>,  cudaFuncAttributeMaxDynamicSharedMemorySize, SMEM_G32);
        cudaFuncSetAttribute(k_wgemmBig,   cudaFuncAttributeMaxDynamicSharedMemorySize, SMEM_BIG);
        attrDone = true;
    }

    __half *WpH,*WpL;
    __nv_bfloat16 *annSH,*annSL,*WhcH,*WhcL,*Wc2H,*Wc2L;
    __nv_bfloat16 *Wih1H,*Wih1L,*Wih2H,*Wih2L,*WhH,*WhL,*EmbH,*EmbL,*a0H,*a0L,*hsH,*hsL;
    float *annProj,*annIh,*hbase,*giEmb;
    SYM(WpH, d_Wp16H); SYM(WpL, d_Wp16L);
    SYM(annSH, d_annSH); SYM(annSL, d_annSL);
    SYM(WhcH, d_WhcH); SYM(WhcL, d_WhcL);
    SYM(Wc2H, d_Wc2H); SYM(Wc2L, d_Wc2L);
    SYM(Wih1H, d_Wih1H); SYM(Wih1L, d_Wih1L);
    SYM(Wih2H, d_Wih2H); SYM(Wih2L, d_Wih2L);
    SYM(WhH, d_WhH);   SYM(WhL, d_WhL);
    SYM(EmbH, d_EmbH); SYM(EmbL, d_EmbL);
    SYM(a0H, d_a0H);   SYM(a0L, d_a0L);
    SYM(hsH, d_hsH);   SYM(hsL, d_hsL);
    SYM(annProj, d_annProj); SYM(annIh, d_annIh);
    SYM(hbase, d_hbuf); SYM(giEmb, d_giEmb);

    const int C2W = EMBED + DCH + 2 * ECH;   // 3620
    const int WIHW = EMBED + 2 * ECH;        // 2620

    auto split = [](const float* s, int sld, int off, int rows, int cols,
                    __nv_bfloat16* hi, __nv_bfloat16* lo, int dld) {
        long long tot8 = ((long long)rows * dld) >> 3;
        k_split8<<<(unsigned)((tot8 + 255) / 256), 256>>>(s, sld, off, rows, cols, hi, lo, dld);
    };
    // fp16 split of W_p
    {
        long long tot8 = ((long long)VOCAB * KP_WP) >> 3;
        k_splitH8<<<(unsigned)((tot8 + 255) / 256), 256>>>(W_p, C2W, 0, VOCAB, C2W, WpH, WpL, KP_WP);
    }
    split(W_hh, DCH, 0, 3 * DCH, DCH, WhcH, WhcL, KP_H);
    split(W_c, DCH + 2 * ECH, 0, DCH, DCH, WhcH + (size_t)3*DCH*KP_H,
          WhcL + (size_t)3*DCH*KP_H, KP_H);
    split(W_c, DCH + 2 * ECH, DCH, DCH, 2 * ECH, Wc2H, Wc2L, KP_CTX);
    split(W_ih, WIHW, 0,     3 * DCH, EMBED,   Wih1H, Wih1L, KP_EMB);
    split(W_ih, WIHW, EMBED, 3 * DCH, 2 * ECH, Wih2H, Wih2L, KP_CTX);
    split(W_h, ECH, 0, DCH, ECH, WhH, WhL, KP_H);
    split(ann, 2 * ECH, 0,   SRC * BSZ, 2 * ECH, annSH, annSL, KP_CTX);
    split(ann, 2 * ECH, ECH, BSZ, ECH, a0H, a0L, KP_H);
    k_bcomb<<<(NGH + 255) / 256, 256>>>(b_hh);
    k_zero<<<(BSZ * VOCAB + 255) / 256, 256>>>(preds, attns, BSZ * VOCAB);
    k_embedS<<<(MROWS * KP_EMB + 255) / 256, 256>>>(tok, emb);

    // h0 = tanh(ann0_bw @ W_h^T + b_h)
    g32(a0H, a0L, KP_H, WhH, WhL, KP_H, b_h, nullptr, 0, hbase, DCH, BSZ, DCH, KP_H, 1);
    split(hbase, DCH, 0, BSZ, DCH, hsH, hsL, KP_H);

    // annProj = ann @ W_c2^T + b_c
    g128(annSH, annSL, KP_CTX, Wc2H, Wc2L, KP_CTX, b_c, nullptr, 0,
         annProj, DCH, SRC * BSZ, DCH, KP_CTX, 0);
    // giEmb = embedded @ W_ih1^T + b_ih
    g128(EmbH, EmbL, KP_EMB, Wih1H, Wih1L, KP_EMB, b_ih, nullptr, 0,
         giEmb, 3 * DCH, MROWS, 3 * DCH, KP_EMB, 0);
    // annIh = ann @ W_ih2^T
    g128(annSH, annSL, KP_CTX, Wih2H, Wih2L, KP_CTX, nullptr, nullptr, 0,
         annIh, 3 * DCH, SRC * BSZ, 3 * DCH, KP_CTX, 0);

    // persistent 49-step recurrence (single launch)
    k_recur<<<RGRID, 256>>>(ann, w_a, attns, hidden);

    // big prediction GEMM (fp16, 2 products, 2 CTA/SM) -> scratch, then bias+log_softmax -> preds
    {
        dim3 g(LROWS / 128, LCOLS / 256);   // 13 x 118
        k_wgemmBig<<<g, 256, SMEM_BIG>>>();
    }
    k_lsm<<<MROWS, 256>>>(b_p, preds);
}

// round 14
// speedup vs baseline: 1.6297x; 1.6297x over previous
#include <cuda_runtime.h>
#include <cuda_bf16.h>
#include <cuda_fp16.h>
#include <mma.h>
#include <math.h>
#include <stdint.h>

using namespace nvcuda;

#define SRC 50
#define TRGN 50
#define BSZ 32
#define EMBED 620
#define ECH 1000
#define DCH 1000
#define VOCAB 30000
#define NSTEP 49
#define MROWS (NSTEP*BSZ)          /* 1568 */
#define KP_WP 3648
#define KP_CTX 2048
#define KP_H 1024
#define KP_EMB 640
#define NGH 4000
#define RGRID 64
#define LROWS 1664
#define LCOLS 30208

// ============================ static scratch (bss, zero-initialized) ============================
__device__ __half d_Wp16H[(size_t)VOCAB*KP_WP], d_Wp16L[(size_t)VOCAB*KP_WP];  // W_p fp16 hi/lo
__device__ __half d_C2[(size_t)MROWS*KP_WP];                                    // comb2, single fp16
__device__ __nv_bfloat16 d_annSH[(size_t)SRC*BSZ*KP_CTX], d_annSL[(size_t)SRC*BSZ*KP_CTX];
__device__ __nv_bfloat16 d_WhcH[(size_t)NGH*KP_H], d_WhcL[(size_t)NGH*KP_H];
__device__ __nv_bfloat16 d_Wc2H[(size_t)DCH*KP_CTX], d_Wc2L[(size_t)DCH*KP_CTX];
__device__ __nv_bfloat16 d_Wih1H[(size_t)3*DCH*KP_EMB], d_Wih1L[(size_t)3*DCH*KP_EMB];
__device__ __nv_bfloat16 d_Wih2H[(size_t)3*DCH*KP_CTX], d_Wih2L[(size_t)3*DCH*KP_CTX];
__device__ __nv_bfloat16 d_WhH[DCH*KP_H], d_WhL[DCH*KP_H];
__device__ __nv_bfloat16 d_EmbH[(size_t)MROWS*KP_EMB], d_EmbL[(size_t)MROWS*KP_EMB];
__device__ __nv_bfloat16 d_a0H[BSZ*KP_H], d_a0L[BSZ*KP_H];
__device__ __nv_bfloat16 d_hsH[2][BSZ*KP_H], d_hsL[2][BSZ*KP_H];
__device__ float d_annProj[SRC*BSZ*DCH];
__device__ float d_annIh[(size_t)SRC*BSZ*3*DCH];
__device__ float d_hbuf[2][BSZ*DCH];
__device__ float d_ghp[BSZ*NGH];
__device__ float d_attnS[SRC*BSZ];
__device__ float d_giEmb[(size_t)MROWS*3*DCH];
__device__ float d_bcomb[NGH];
__device__ float d_logits[(size_t)LROWS*LCOLS];

__device__ int g_cnt;
__device__ volatile int g_gen;

// ============================ helpers ============================
__device__ __forceinline__ uint32_t smem_u32(const void* p) {
    uint32_t a;
    asm("{ .reg .u64 t; cvta.to.shared.u64 t, %1; cvt.u32.u64 %0, t; }" : "=r"(a) : "l"(p));
    return a;
}
__device__ __forceinline__ void cp_async16(uint32_t dst, const void* src) {
    asm volatile("cp.async.cg.shared.global [%0], [%1], 16;\n" :: "r"(dst), "l"(src));
}
__device__ __forceinline__ void cp_commit() {
    asm volatile("cp.async.commit_group;\n" ::: "memory");
}
__device__ __forceinline__ void gridbar() {
    __syncthreads();
    if (threadIdx.x == 0) {
        __threadfence();
        int gen = g_gen;
        if (atomicAdd(&g_cnt, 1) == RGRID - 1) {
            g_cnt = 0;
            __threadfence();
            g_gen = gen + 1;
        } else {
            while (g_gen == gen) { __nanosleep(64); }
        }
        __threadfence();
    }
    __syncthreads();
}

// ============================ BIG GEMM: fp16 2-product, 128x256 tile, K-chunk 64, 3-stage, 1 CTA/SM ============================
// logits = C2 @ (Wp16H + Wp16L)^T  (A rounded once to fp16; B exact fp16 split)
#define BLDT 72
#define BSTAGE ((128 + 256) * BLDT)
#define SMEM_BIG (3 * BSTAGE * 2)

__global__ __launch_bounds__(256, 1) void k_wgemmBig()
{
    extern __shared__ __half tiles[];
    const int tid = threadIdx.x, wid = tid >> 5;
    const int m0 = blockIdx.x * 128, n0 = blockIdx.y * 256;
    const int wm = wid & 1, wn = wid >> 1;
    const int wmo = wm * 64, wno = wn * 64;

    wmma::fragment<wmma::accumulator, 16, 16, 16, float> acc[4][4];
#pragma unroll
    for (int i = 0; i < 4; i++)
#pragma unroll
        for (int j = 0; j < 4; j++) wmma::fill_fragment(acc[i][j], 0.0f);

    const int cpp = KP_WP >> 6;        // 57
    const int total = 2 * cpp;         // 114: products C2*WpH, C2*WpL

    auto prefetch = [&](int c, int stage) {
        int p = c / cpp;
        int kc = (c - p * cpp) << 6;
        const __half* Bp = (p == 0) ? d_Wp16H : d_Wp16L;
        __half* As = tiles + stage * BSTAGE;
        __half* Bs = As + 128 * BLDT;
#pragma unroll
        for (int q = 0; q < 4; q++) {          // A: 128 rows x 8 segs
            int it = tid + q * 256;
            int r = it >> 3, s = it & 7;
            int gm = m0 + r; if (gm >= MROWS) gm = MROWS - 1;
            cp_async16(smem_u32(As + r * BLDT + s * 8), d_C2 + (size_t)gm * KP_WP + kc + s * 8);
        }
#pragma unroll
        for (int q = 0; q < 8; q++) {          // B: 256 rows x 8 segs
            int it = tid + q * 256;
            int r = it >> 3, s = it & 7;
            int gn = n0 + r; if (gn >= VOCAB) gn = VOCAB - 1;
            cp_async16(smem_u32(Bs + r * BLDT + s * 8), Bp + (size_t)gn * KP_WP + kc + s * 8);
        }
        cp_commit();
    };

    prefetch(0, 0);
    prefetch(1, 1);

    for (int c = 0; c < total; c++) {
        if (c + 1 < total) { asm volatile("cp.async.wait_group 1;\n" ::: "memory"); }
        else               { asm volatile("cp.async.wait_group 0;\n" ::: "memory"); }
        __syncthreads();
        if (c + 2 < total) prefetch(c + 2, (c + 2) % 3);
        const __half* As = tiles + (c % 3) * BSTAGE;
        const __half* Bs = As + 128 * BLDT;
#pragma unroll
        for (int kk = 0; kk < 64; kk += 16) {
            wmma::fragment<wmma::matrix_a, 16,16,16, __half, wmma::row_major> af[4];
            wmma::fragment<wmma::matrix_b, 16,16,16, __half, wmma::col_major> bf[4];
#pragma unroll
            for (int i = 0; i < 4; i++)
                wmma::load_matrix_sync(af[i], As + (wmo + i * 16) * BLDT + kk, BLDT);
#pragma unroll
            for (int j = 0; j < 4; j++)
                wmma::load_matrix_sync(bf[j], Bs + (wno + j * 16) * BLDT + kk, BLDT);
#pragma unroll
            for (int i = 0; i < 4; i++)
#pragma unroll
                for (int j = 0; j < 4; j++)
                    wmma::mma_sync(acc[i][j], af[i], bf[j], acc[i][j]);
        }
        __syncthreads();
    }

#pragma unroll
    for (int i = 0; i < 4; i++)
#pragma unroll
        for (int j = 0; j < 4; j++)
            wmma::store_matrix_sync(d_logits + (size_t)(m0 + wmo + i * 16) * LCOLS + n0 + wno + j * 16,
                                    acc[i][j], LCOLS, wmma::mem_row_major);
}

// ============================ generic WMMA bf16 split GEMM (2-stage, LDT 40) ============================
template<int BM>
__global__ __launch_bounds__(256) void k_wgemm(
    const __nv_bfloat16* __restrict__ Ah, const __nv_bfloat16* __restrict__ Al, int lda,
    const __nv_bfloat16* __restrict__ Bh, const __nv_bfloat16* __restrict__ Bl, int ldb,
    const float* __restrict__ bias,
    const float* __restrict__ Dadd, int ldd,
    float* __restrict__ C, int ldc,
    int M, int N, int KP, int act)
{
    constexpr int MFR = (BM == 128) ? 2 : 1;
    constexpr int NFR = (BM == 128) ? 4 : 2;
    constexpr int AITEMS = BM * 4;
    constexpr int LDT = 40;
    constexpr int LDC_S = 136;
    constexpr int STAGE = (BM + 128) * LDT;

    extern __shared__ char smem[];
    __nv_bfloat16* tiles = (__nv_bfloat16*)smem;
    float* Cs = (float*)smem;

    const int tid = threadIdx.x, wid = tid >> 5;
    const int m0 = blockIdx.x * BM, n0 = blockIdx.y * 128;

    int wm, wn;
    if (BM == 128) { wm = wid & 3; wn = wid >> 2; }
    else           { wm = wid & 1; wn = wid >> 1; }
    const int wrow = wm * (16 * MFR);
    const int wcol = wn * (16 * NFR);

    wmma::fragment<wmma::accumulator, 16, 16, 16, float> acc[MFR][NFR];
#pragma unroll
    for (int i = 0; i < MFR; i++)
#pragma unroll
        for (int j = 0; j < NFR; j++)
            wmma::fill_fragment(acc[i][j], 0.0f);

    const int cpp = KP >> 5;
    const int total = 3 * cpp;

    auto prefetch = [&](int c, int stage) {
        int p = c / cpp;
        int kc = (c - p * cpp) << 5;
        const __nv_bfloat16* Ap = (p < 2) ? Ah : Al;
        const __nv_bfloat16* Bp = (p == 1) ? Bl : Bh;
        __nv_bfloat16* As = tiles + stage * STAGE;
        __nv_bfloat16* Bs = As + BM * LDT;
#pragma unroll
        for (int q = 0; q < (BM == 128 ? 2 : 1); q++) {
            int it = tid + q * 256;
            if (BM == 32 && it >= AITEMS) break;
            int r = it >> 2, seg = it & 3;
            int gm = m0 + r; if (gm >= M) gm = M - 1;
            cp_async16(smem_u32(As + r * LDT + seg * 8), Ap + (size_t)gm * lda + kc + seg * 8);
        }
#pragma unroll
        for (int q = 0; q < 2; q++) {
            int it = tid + q * 256;
            int r = it >> 2, seg = it & 3;
            int gn = n0 + r; if (gn >= N) gn = N - 1;
            cp_async16(smem_u32(Bs + r * LDT + seg * 8), Bp + (size_t)gn * ldb + kc + seg * 8);
        }
        cp_commit();
    };

    prefetch(0, 0);
    prefetch(1, 1);

    for (int c = 0; c < total; c++) {
        if (c + 1 < total) { asm volatile("cp.async.wait_group 1;\n" ::: "memory"); }
        else               { asm volatile("cp.async.wait_group 0;\n" ::: "memory"); }
        __syncthreads();
        const __nv_bfloat16* As = tiles + (c & 1) * STAGE;
        const __nv_bfloat16* Bs = As + BM * LDT;
#pragma unroll
        for (int kk = 0; kk < 32; kk += 16) {
            wmma::fragment<wmma::matrix_a, 16,16,16, __nv_bfloat16, wmma::row_major> af[MFR];
            wmma::fragment<wmma::matrix_b, 16,16,16, __nv_bfloat16, wmma::col_major> bf[NFR];
#pragma unroll
            for (int i = 0; i < MFR; i++)
                wmma::load_matrix_sync(af[i], As + (wrow + i * 16) * LDT + kk, LDT);
#pragma unroll
            for (int j = 0; j < NFR; j++)
                wmma::load_matrix_sync(bf[j], Bs + (wcol + j * 16) * LDT + kk, LDT);
#pragma unroll
            for (int i = 0; i < MFR; i++)
#pragma unroll
                for (int j = 0; j < NFR; j++)
                    wmma::mma_sync(acc[i][j], af[i], bf[j], acc[i][j]);
        }
        __syncthreads();
        if (c + 2 < total) prefetch(c + 2, c & 1);
    }

#pragma unroll
    for (int i = 0; i < MFR; i++)
#pragma unroll
        for (int j = 0; j < NFR; j++)
            wmma::store_matrix_sync(Cs + (wrow + i * 16) * LDC_S + wcol + j * 16,
                                    acc[i][j], LDC_S, wmma::mem_row_major);
    __syncthreads();
    for (int idx = tid; idx < BM * 128; idx += 256) {
        int r = idx >> 7, cc = idx & 127;
        int gm = m0 + r, gn = n0 + cc;
        if (gm < M && gn < N) {
            float v = Cs[r * LDC_S + cc];
            if (bias) v += bias[gn];
            if (Dadd) v += Dadd[(size_t)gm * ldd + gn];
            if (act)  v = tanhf(v);
            C[(size_t)gm * ldc + gn] = v;
        }
    }
}

// ============================ persistent recurrence kernel ============================
__global__ __launch_bounds__(256) void k_recur(const float* __restrict__ ann,
                                               const float* __restrict__ w_a,
                                               float* __restrict__ attns,
                                               float* __restrict__ hidden)
{
    __shared__ char smr[40192];
    const int bid = blockIdx.x;
    const int tid = threadIdx.x;
    const int wid = tid >> 5;

    __nv_bfloat16* Ath = (__nv_bfloat16*)smr;
    __nv_bfloat16* Atl = Ath + 2 * 32 * 40;
    __nv_bfloat16* Bth = Atl + 2 * 32 * 40;
    __nv_bfloat16* Btl = Bth + 2 * 64 * 40;
    float* Cs = (float*)(Btl + 2 * 64 * 40);
    float* sc  = (float*)smr;
    float* sat = (float*)smr;
    float* sgi = sat + 64;

    for (int step = 0; step < NSTEP; step++) {
        const int cur = step & 1;
        // ---- phase A: ghp = h @ [W_hh; W_c1]^T + bcomb ----
        if (bid < 63) {
            const int n0 = bid * 64;
            const int wm = wid & 1, wn = wid >> 1;
            const __nv_bfloat16* hH = d_hsH[cur];
            const __nv_bfloat16* hL = d_hsL[cur];
            wmma::fragment<wmma::accumulator, 16, 16, 16, float> acc;
            wmma::fill_fragment(acc, 0.0f);
#pragma unroll 1
            for (int c = 0; c < 32; c++) {
                const int st = c & 1;
                const int kc = c << 5;
                {
                    int it = tid & 127;
                    int r = it >> 2, seg = it & 3;
                    const __nv_bfloat16* src = (tid < 128) ? hH : hL;
                    __nv_bfloat16* dst = ((tid < 128) ? Ath : Atl) + st * (32 * 40);
                    *(uint4*)(dst + r * 40 + seg * 8) =
                        *(const uint4*)(src + (size_t)r * KP_H + kc + seg * 8);
                }
#pragma unroll
                for (int q = 0; q < 2; q++) {
                    int it = tid + q * 256;
                    int r = (it & 255) >> 2, seg = it & 3;
                    int gn = n0 + r; if (gn >= NGH) gn = NGH - 1;
                    const __nv_bfloat16* src = (it < 256) ? d_WhcH : d_WhcL;
                    __nv_bfloat16* dst = ((it < 256) ? Bth : Btl) + st * (64 * 40);
                    *(uint4*)(dst + r * 40 + seg * 8) =
                        *(const uint4*)(src + (size_t)gn * KP_H + kc + seg * 8);
                }
                __syncthreads();
#pragma unroll
                for (int kk = 0; kk < 32; kk += 16) {
                    wmma::fragment<wmma::matrix_a, 16,16,16, __nv_bfloat16, wmma::row_major> ah, al;
                    wmma::fragment<wmma::matrix_b, 16,16,16, __nv_bfloat16, wmma::col_major> bh, bl;
                    wmma::load_matrix_sync(ah, Ath + st * (32*40) + (wm * 16) * 40 + kk, 40);
                    wmma::load_matrix_sync(al, Atl + st * (32*40) + (wm * 16) * 40 + kk, 40);
                    wmma::load_matrix_sync(bh, Bth + st * (64*40) + (wn * 16) * 40 + kk, 40);
                    wmma::load_matrix_sync(bl, Btl + st * (64*40) + (wn * 16) * 40 + kk, 40);
                    wmma::mma_sync(acc, ah, bh, acc);
                    wmma::mma_sync(acc, ah, bl, acc);
                    wmma::mma_sync(acc, al, bh, acc);
                }
            }
            __syncthreads();
            wmma::store_matrix_sync(Cs + (wm * 16) * 72 + wn * 16, acc, 72, wmma::mem_row_major);
            __syncthreads();
            for (int idx = tid; idx < 32 * 64; idx += 256) {
                int r = idx >> 6, cc = idx & 63;
                int gn = n0 + cc;
                if (gn < NGH)
                    d_ghp[r * NGH + gn] = Cs[r * 72 + cc] + d_bcomb[gn];
            }
        }
        gridbar();

        // ---- phase B: attention + softmax over batch ----
        if (bid < SRC) {
            const int s = bid;
            int b = tid >> 3, jt = tid & 7;
            const float* hp = d_ghp + b * NGH + 3 * DCH;
            const float* ap = d_annProj + (size_t)(s * BSZ + b) * DCH;
            float acc = 0.f;
            for (int j = jt; j < DCH; j += 8)
                acc += tanhf(hp[j] + ap[j]) * w_a[j];
            for (int off = 4; off; off >>= 1)
                acc += __shfl_down_sync(0xffffffffu, acc, off, 8);
            if (jt == 0) sc[b] = acc;
            __syncthreads();
            if (tid < 32) {
                float v = sc[tid];
                float m = v;
                for (int off = 16; off; off >>= 1) m = fmaxf(m, __shfl_xor_sync(0xffffffffu, m, off));
                float e = expf(v - m);
                float ssum = e;
                for (int off = 16; off; off >>= 1) ssum += __shfl_xor_sync(0xffffffffu, ssum, off);
                float a = e / ssum;
                d_attnS[s * BSZ + tid] = a;
                attns[(size_t)(step + 1) * SRC * BSZ + s * BSZ + tid] = a;
            }
        }
        gridbar();

        // ---- phase C: context + gi + GRU gates ----
        if (bid < BSZ) {
            const int b = bid;
            if (tid < SRC) sat[tid] = d_attnS[tid * BSZ + b];
            __syncthreads();
            for (int e = tid; e < 2 * ECH; e += 256) {
                float acc = 0.f;
                const float* ap = ann + (size_t)b * (2 * ECH) + e;
#pragma unroll 10
                for (int s = 0; s < SRC; s++)
                    acc += sat[s] * ap[(size_t)s * BSZ * (2 * ECH)];
                d_C2[(size_t)(step * BSZ + b) * KP_WP + EMBED + DCH + e] = __float2half(acc);
            }
            const float* gE = d_giEmb + ((size_t)step * BSZ + b) * 3 * DCH;
            for (int j = tid; j < 3 * DCH; j += 256) {
                float acc = gE[j];
                const float* ip = d_annIh + (size_t)b * 3 * DCH + j;
#pragma unroll 10
                for (int s = 0; s < SRC; s++)
                    acc += sat[s] * ip[(size_t)s * BSZ * 3 * DCH];
                sgi[j] = acc;
            }
            __syncthreads();
            const float* gh = d_ghp + b * NGH;
            for (int j = tid; j < DCH; j += 256) {
                float r = 1.f / (1.f + expf(-(sgi[j] + gh[j])));
                float z = 1.f / (1.f + expf(-(sgi[DCH + j] + gh[DCH + j])));
                float n = tanhf(sgi[2 * DCH + j] + r * gh[2 * DCH + j]);
                float hp = d_hbuf[cur][b * DCH + j];
                float hn = (1.f - z) * n + z * hp;
                d_hbuf[cur ^ 1][b * DCH + j] = hn;
                __nv_bfloat16 hh = __float2bfloat16(hn);
                d_hsH[cur ^ 1][b * KP_H + j] = hh;
                d_hsL[cur ^ 1][b * KP_H + j] = __float2bfloat16(hn - __bfloat162float(hh));
                d_C2[(size_t)(step * BSZ + b) * KP_WP + EMBED + j] = __float2half(hp);
                if (step == NSTEP - 1) hidden[b * DCH + j] = hn;
            }
        }
        gridbar();
    }
}

// ============================ small kernels ============================
__global__ void k_split8(const float* __restrict__ src, int sld, int colOff, int rows, int cols,
                         __nv_bfloat16* __restrict__ hi, __nv_bfloat16* __restrict__ lo, int dld)
{
    int i8 = blockIdx.x * blockDim.x + threadIdx.x;
    int total8 = (rows * dld) >> 3;
    if (i8 >= total8) return;
    int i = i8 << 3;
    int r = i / dld, c = i - r * dld;
    float x[8];
    if (c + 7 < cols) {
        const float* p = src + (size_t)r * sld + colOff + c;
        *(float4*)(x)     = *(const float4*)(p);
        *(float4*)(x + 4) = *(const float4*)(p + 4);
    } else {
#pragma unroll
        for (int q = 0; q < 8; q++)
            x[q] = (c + q < cols) ? src[(size_t)r * sld + colOff + c + q] : 0.f;
    }
    __nv_bfloat16 h[8], l[8];
#pragma unroll
    for (int q = 0; q < 8; q++) {
        h[q] = __float2bfloat16(x[q]);
        l[q] = __float2bfloat16(x[q] - __bfloat162float(h[q]));
    }
    *(uint4*)(hi + i) = *(uint4*)h;
    *(uint4*)(lo + i) = *(uint4*)l;
}

// fp16 hi/lo split, 8 elems/thread (W_p)
__global__ void k_splitH8(const float* __restrict__ src, int sld, int colOff, int rows, int cols,
                          __half* __restrict__ hi, __half* __restrict__ lo, int dld)
{
    int i8 = blockIdx.x * blockDim.x + threadIdx.x;
    int total8 = (rows * dld) >> 3;
    if (i8 >= total8) return;
    int i = i8 << 3;
    int r = i / dld, c = i - r * dld;
    float x[8];
    if (c + 7 < cols) {
        const float* p = src + (size_t)r * sld + colOff + c;
        *(float4*)(x)     = *(const float4*)(p);
        *(float4*)(x + 4) = *(const float4*)(p + 4);
    } else {
#pragma unroll
        for (int q = 0; q < 8; q++)
            x[q] = (c + q < cols) ? src[(size_t)r * sld + colOff + c + q] : 0.f;
    }
    __half h[8], l[8];
#pragma unroll
    for (int q = 0; q < 8; q++) {
        h[q] = __float2half(x[q]);
        l[q] = __float2half(x[q] - __half2float(h[q]));
    }
    *(uint4*)(hi + i) = *(uint4*)h;
    *(uint4*)(lo + i) = *(uint4*)l;
}

__global__ void k_zero(float* __restrict__ preds0, float* __restrict__ attns0, int n)
{
    int i = blockIdx.x * blockDim.x + threadIdx.x;
    if (i < n) preds0[i] = 0.f;
    if (i < SRC * BSZ) attns0[i] = 0.f;
}

__global__ void k_bcomb(const float* __restrict__ b_hh)
{
    int i = blockIdx.x * blockDim.x + threadIdx.x;
    if (i < NGH) d_bcomb[i] = (i < 3 * DCH) ? b_hh[i] : 0.f;
}

__global__ void k_embedS(const int* __restrict__ tok, const float* __restrict__ emb)
{
    int i = blockIdx.x * blockDim.x + threadIdx.x;
    if (i >= MROWS * KP_EMB) return;
    int m = i / KP_EMB, e = i - m * KP_EMB;
    float x = (e < EMBED) ? emb[(size_t)tok[m] * EMBED + e] : 0.f;
    __nv_bfloat16 h = __float2bfloat16(x);
    d_EmbH[i] = h;
    d_EmbL[i] = __float2bfloat16(x - __bfloat162float(h));
    if (e < EMBED)
        d_C2[(size_t)m * KP_WP + e] = __float2half(x);
}

__global__ __launch_bounds__(256) void k_lsm(const float* __restrict__ bias, float* __restrict__ preds)
{
    int m = blockIdx.x;
    const float* row = d_logits + (size_t)m * LCOLS;
    float* outr = preds + (size_t)(m + BSZ) * VOCAB;
    int t = threadIdx.x;
    __shared__ float rm[256], rs[256];
    float mx = -1e30f, sum = 0.f;
    for (int v = t; v < VOCAB; v += 256) {
        float x = row[v] + bias[v];
        if (x > mx) { sum = sum * expf(mx - x) + 1.f; mx = x; }
        else sum += expf(x - mx);
    }
    rm[t] = mx; rs[t] = sum; __syncthreads();
    for (int s2 = 128; s2; s2 >>= 1) {
        if (t < s2) {
            float m1 = rm[t], m2 = rm[t + s2];
            float M = fmaxf(m1, m2);
            rs[t] = rs[t] * expf(m1 - M) + rs[t + s2] * expf(m2 - M);
            rm[t] = M;
        }
        __syncthreads();
    }
    float lse = rm[0] + logf(rs[0]);
    for (int v = t; v < VOCAB; v += 256)
        outr[v] = row[v] + bias[v] - lse;
}

// ============================ host ============================
#define SYM(p, s) do { void* _t; cudaGetSymbolAddress(&_t, s); p = (decltype(p))_t; } while (0)

#define SMEM_G128 (128 * 136 * 4)
#define SMEM_G32  (2 * (32 + 128) * 40 * 2 + 1024)

static inline void g128(const __nv_bfloat16* Ah, const __nv_bfloat16* Al, int lda,
                        const __nv_bfloat16* Bh, const __nv_bfloat16* Bl, int ldb,
                        const float* bias, const float* Dadd, int ldd,
                        float* C, int ldc, int M, int N, int KP, int act)
{
    dim3 g((M + 127) / 128, (N + 127) / 128);
    k_wgemm<128><<<g, 256, SMEM_G128>>>(Ah, Al, lda, Bh, Bl, ldb, bias, Dadd, ldd, C, ldc, M, N, KP, act);
}
static inline void g32(const __nv_bfloat16* Ah, const __nv_bfloat16* Al, int lda,
                       const __nv_bfloat16* Bh, const __nv_bfloat16* Bl, int ldb,
                       const float* bias, const float* Dadd, int ldd,
                       float* C, int ldc, int M, int N, int KP, int act)
{
    dim3 g((M + 31) / 32, (N + 127) / 128);
    k_wgemm<32><<<g, 256, SMEM_G32>>>(Ah, Al, lda, Bh, Bl, ldb, bias, Dadd, ldd, C, ldc, M, N, KP, act);
}

extern "C" void kernel_launch(void* const* d_in, const int* in_sizes, int n_in,
                              void* d_out, int out_size)
{
    (void)in_sizes; (void)n_in; (void)out_size;
    const int*   tok  = (const int*)  d_in[0];
    const float* ann  = (const float*)d_in[1];
    const float* emb  = (const float*)d_in[2];
    const float* W_h  = (const float*)d_in[3];
    const float* b_h  = (const float*)d_in[4];
    const float* W_c  = (const float*)d_in[5];
    const float* b_c  = (const float*)d_in[6];
    const float* w_a  = (const float*)d_in[7];
    const float* W_ih = (const float*)d_in[8];
    const float* W_hh = (const float*)d_in[9];
    const float* b_ih = (const float*)d_in[10];
    const float* b_hh = (const float*)d_in[11];
    const float* W_p  = (const float*)d_in[12];
    const float* b_p  = (const float*)d_in[13];

    float* out    = (float*)d_out;
    float* preds  = out;
    float* hidden = out + (size_t)TRGN * BSZ * VOCAB;
    float* attns  = hidden + BSZ * DCH;

    static bool attrDone = false;
    if (!attrDone) {
        cudaFuncSetAttribute(k_wgemm<128>, cudaFuncAttributeMaxDynamicSharedMemorySize, SMEM_G128);
        cudaFuncSetAttribute(k_wgemm<32>,  cudaFuncAttributeMaxDynamicSharedMemorySize, SMEM_G32);
        cudaFuncSetAttribute(k_wgemmBig,   cudaFuncAttributeMaxDynamicSharedMemorySize, SMEM_BIG);
        attrDone = true;
    }

    __half *WpH,*WpL;
    __nv_bfloat16 *annSH,*annSL,*WhcH,*WhcL,*Wc2H,*Wc2L;
    __nv_bfloat16 *Wih1H,*Wih1L,*Wih2H,*Wih2L,*WhH,*WhL,*EmbH,*EmbL,*a0H,*a0L,*hsH,*hsL;
    float *annProj,*annIh,*hbase,*giEmb;
    SYM(WpH, d_Wp16H); SYM(WpL, d_Wp16L);
    SYM(annSH, d_annSH); SYM(annSL, d_annSL);
    SYM(WhcH, d_WhcH); SYM(WhcL, d_WhcL);
    SYM(Wc2H, d_Wc2H); SYM(Wc2L, d_Wc2L);
    SYM(Wih1H, d_Wih1H); SYM(Wih1L, d_Wih1L);
    SYM(Wih2H, d_Wih2H); SYM(Wih2L, d_Wih2L);
    SYM(WhH, d_WhH);   SYM(WhL, d_WhL);
    SYM(EmbH, d_EmbH); SYM(EmbL, d_EmbL);
    SYM(a0H, d_a0H);   SYM(a0L, d_a0L);
    SYM(hsH, d_hsH);   SYM(hsL, d_hsL);
    SYM(annProj, d_annProj); SYM(annIh, d_annIh);
    SYM(hbase, d_hbuf); SYM(giEmb, d_giEmb);

    const int C2W = EMBED + DCH + 2 * ECH;   // 3620
    const int WIHW = EMBED + 2 * ECH;        // 2620

    auto split = [](const float* s, int sld, int off, int rows, int cols,
                    __nv_bfloat16* hi, __nv_bfloat16* lo, int dld) {
        long long tot8 = ((long long)rows * dld) >> 3;
        k_split8<<<(unsigned)((tot8 + 255) / 256), 256>>>(s, sld, off, rows, cols, hi, lo, dld);
    };
    // fp16 split of W_p
    {
        long long tot8 = ((long long)VOCAB * KP_WP) >> 3;
        k_splitH8<<<(unsigned)((tot8 + 255) / 256), 256>>>(W_p, C2W, 0, VOCAB, C2W, WpH, WpL, KP_WP);
    }
    split(W_hh, DCH, 0, 3 * DCH, DCH, WhcH, WhcL, KP_H);
    split(W_c, DCH + 2 * ECH, 0, DCH, DCH, WhcH + (size_t)3*DCH*KP_H,
          WhcL + (size_t)3*DCH*KP_H, KP_H);
    split(W_c, DCH + 2 * ECH, DCH, DCH, 2 * ECH, Wc2H, Wc2L, KP_CTX);
    split(W_ih, WIHW, 0,     3 * DCH, EMBED,   Wih1H, Wih1L, KP_EMB);
    split(W_ih, WIHW, EMBED, 3 * DCH, 2 * ECH, Wih2H, Wih2L, KP_CTX);
    split(W_h, ECH, 0, DCH, ECH, WhH, WhL, KP_H);
    split(ann, 2 * ECH, 0,   SRC * BSZ, 2 * ECH, annSH, annSL, KP_CTX);
    split(ann, 2 * ECH, ECH, BSZ, ECH, a0H, a0L, KP_H);
    k_bcomb<<<(NGH + 255) / 256, 256>>>(b_hh);
    k_zero<<<(BSZ * VOCAB + 255) / 256, 256>>>(preds, attns, BSZ * VOCAB);
    k_embedS<<<(MROWS * KP_EMB + 255) / 256, 256>>>(tok, emb);

    // h0 = tanh(ann0_bw @ W_h^T + b_h)
    g32(a0H, a0L, KP_H, WhH, WhL, KP_H, b_h, nullptr, 0, hbase, DCH, BSZ, DCH, KP_H, 1);
    split(hbase, DCH, 0, BSZ, DCH, hsH, hsL, KP_H);

    // annProj = ann @ W_c2^T + b_c
    g128(annSH, annSL, KP_CTX, Wc2H, Wc2L, KP_CTX, b_c, nullptr, 0,
         annProj, DCH, SRC * BSZ, DCH, KP_CTX, 0);
    // giEmb = embedded @ W_ih1^T + b_ih
    g128(EmbH, EmbL, KP_EMB, Wih1H, Wih1L, KP_EMB, b_ih, nullptr, 0,
         giEmb, 3 * DCH, MROWS, 3 * DCH, KP_EMB, 0);
    // annIh = ann @ W_ih2^T
    g128(annSH, annSL, KP_CTX, Wih2H, Wih2L, KP_CTX, nullptr, nullptr, 0,
         annIh, 3 * DCH, SRC * BSZ, 3 * DCH, KP_CTX, 0);

    // persistent 49-step recurrence (single launch)
    k_recur<<<RGRID, 256>>>(ann, w_a, attns, hidden);

    // big prediction GEMM (fp16, 2 products) -> padded scratch, then bias+log_softmax -> preds
    {
        dim3 g(LROWS / 128, LCOLS / 256);   // 13 x 118
        k_wgemmBig<<<g, 256, SMEM_BIG>>>();
    }
    k_lsm<<<MROWS, 256>>>(b_p, preds);
}

// round 15
// speedup vs baseline: 1.6511x; 1.0131x over previous
#include <cuda_runtime.h>
#include <cuda_bf16.h>
#include <cuda_fp16.h>
#include <mma.h>
#include <math.h>
#include <stdint.h>

using namespace nvcuda;

#define SRC 50
#define TRGN 50
#define BSZ 32
#define EMBED 620
#define ECH 1000
#define DCH 1000
#define VOCAB 30000
#define NSTEP 49
#define MROWS (NSTEP*BSZ)          /* 1568 */
#define KP_WP 3648
#define KP_CTX 2048
#define KP_H 1024
#define KP_EMB 640
#define NGH 4000
#define RGRID 64
#define LROWS 1664
#define LCOLS 30208
#define MT 13                      /* M tiles */
#define NT 118                     /* N tiles */
#define NTILES (MT*NT)             /* 1534 */
#define PGRID 148                  /* persistent CTAs */

// ============================ static scratch (bss, zero-initialized) ============================
__device__ __half d_Wp16H[(size_t)VOCAB*KP_WP], d_Wp16L[(size_t)VOCAB*KP_WP];  // W_p fp16 hi/lo
__device__ __half d_C2[(size_t)MROWS*KP_WP];                                    // comb2, single fp16
__device__ __nv_bfloat16 d_annSH[(size_t)SRC*BSZ*KP_CTX], d_annSL[(size_t)SRC*BSZ*KP_CTX];
__device__ __nv_bfloat16 d_WhcH[(size_t)NGH*KP_H], d_WhcL[(size_t)NGH*KP_H];
__device__ __nv_bfloat16 d_Wc2H[(size_t)DCH*KP_CTX], d_Wc2L[(size_t)DCH*KP_CTX];
__device__ __nv_bfloat16 d_Wih1H[(size_t)3*DCH*KP_EMB], d_Wih1L[(size_t)3*DCH*KP_EMB];
__device__ __nv_bfloat16 d_Wih2H[(size_t)3*DCH*KP_CTX], d_Wih2L[(size_t)3*DCH*KP_CTX];
__device__ __nv_bfloat16 d_WhH[DCH*KP_H], d_WhL[DCH*KP_H];
__device__ __nv_bfloat16 d_EmbH[(size_t)MROWS*KP_EMB], d_EmbL[(size_t)MROWS*KP_EMB];
__device__ __nv_bfloat16 d_a0H[BSZ*KP_H], d_a0L[BSZ*KP_H];
__device__ __nv_bfloat16 d_hsH[2][BSZ*KP_H], d_hsL[2][BSZ*KP_H];
__device__ float d_annProj[SRC*BSZ*DCH];
__device__ float d_annIh[(size_t)SRC*BSZ*3*DCH];
__device__ float d_hbuf[2][BSZ*DCH];
__device__ float d_ghp[BSZ*NGH];
__device__ float d_attnS[SRC*BSZ];
__device__ float d_giEmb[(size_t)MROWS*3*DCH];
__device__ float d_bcomb[NGH];
__device__ float d_logits[(size_t)LROWS*LCOLS];

__device__ int g_cnt;
__device__ volatile int g_gen;

// ============================ helpers ============================
__device__ __forceinline__ uint32_t smem_u32(const void* p) {
    uint32_t a;
    asm("{ .reg .u64 t; cvta.to.shared.u64 t, %1; cvt.u32.u64 %0, t; }" : "=r"(a) : "l"(p));
    return a;
}
__device__ __forceinline__ void cp_async16(uint32_t dst, const void* src) {
    asm volatile("cp.async.cg.shared.global [%0], [%1], 16;\n" :: "r"(dst), "l"(src));
}
__device__ __forceinline__ void cp_commit() {
    asm volatile("cp.async.commit_group;\n" ::: "memory");
}
__device__ __forceinline__ void gridbar() {
    __syncthreads();
    if (threadIdx.x == 0) {
        __threadfence();
        int gen = g_gen;
        if (atomicAdd(&g_cnt, 1) == RGRID - 1) {
            g_cnt = 0;
            __threadfence();
            g_gen = gen + 1;
        } else {
            while (g_gen == gen) { __nanosleep(64); }
        }
        __threadfence();
    }
    __syncthreads();
}

// ============================ BIG GEMM: fp16 2-product, persistent 148 CTAs, 128x256 tile, K64, 3-stage ============================
// logits = C2 @ (Wp16H + Wp16L)^T  (A rounded once to fp16; B exact fp16 split)
#define BLDT 72
#define BSTAGE ((128 + 256) * BLDT)
#define SMEM_BIG (3 * BSTAGE * 2)

__global__ __launch_bounds__(256, 1) void k_wgemmBig()
{
    extern __shared__ __half tiles[];
    const int tid = threadIdx.x, wid = tid >> 5;
    const int wm = wid & 1, wn = wid >> 1;
    const int wmo = wm * 64, wno = wn * 64;

    const int cpp = KP_WP >> 6;        // 57
    const int total = 2 * cpp;         // 114: products C2*WpH, C2*WpL

    auto prefetch = [&](int m0, int n0, int c, int stage) {
        int p = c / cpp;
        int kc = (c - p * cpp) << 6;
        const __half* Bp = (p == 0) ? d_Wp16H : d_Wp16L;
        __half* As = tiles + stage * BSTAGE;
        __half* Bs = As + 128 * BLDT;
#pragma unroll
        for (int q = 0; q < 4; q++) {          // A: 128 rows x 8 segs
            int it = tid + q * 256;
            int r = it >> 3, s = it & 7;
            int gm = m0 + r; if (gm >= MROWS) gm = MROWS - 1;
            cp_async16(smem_u32(As + r * BLDT + s * 8), d_C2 + (size_t)gm * KP_WP + kc + s * 8);
        }
#pragma unroll
        for (int q = 0; q < 8; q++) {          // B: 256 rows x 8 segs
            int it = tid + q * 256;
            int r = it >> 3, s = it & 7;
            int gn = n0 + r; if (gn >= VOCAB) gn = VOCAB - 1;
            cp_async16(smem_u32(Bs + r * BLDT + s * 8), Bp + (size_t)gn * KP_WP + kc + s * 8);
        }
        cp_commit();
    };

    for (int t = blockIdx.x; t < NTILES; t += PGRID) {
        const int m0 = (t % MT) * 128;
        const int n0 = (t / MT) * 256;

        wmma::fragment<wmma::accumulator, 16, 16, 16, float> acc[4][4];
#pragma unroll
        for (int i = 0; i < 4; i++)
#pragma unroll
            for (int j = 0; j < 4; j++) wmma::fill_fragment(acc[i][j], 0.0f);

        prefetch(m0, n0, 0, 0);
        prefetch(m0, n0, 1, 1);

        for (int c = 0; c < total; c++) {
            if (c + 1 < total) { asm volatile("cp.async.wait_group 1;\n" ::: "memory"); }
            else               { asm volatile("cp.async.wait_group 0;\n" ::: "memory"); }
            __syncthreads();
            if (c + 2 < total) prefetch(m0, n0, c + 2, (c + 2) % 3);
            const __half* As = tiles + (c % 3) * BSTAGE;
            const __half* Bs = As + 128 * BLDT;
#pragma unroll
            for (int kk = 0; kk < 64; kk += 16) {
                wmma::fragment<wmma::matrix_a, 16,16,16, __half, wmma::row_major> af[4];
                wmma::fragment<wmma::matrix_b, 16,16,16, __half, wmma::col_major> bf[4];
#pragma unroll
                for (int i = 0; i < 4; i++)
                    wmma::load_matrix_sync(af[i], As + (wmo + i * 16) * BLDT + kk, BLDT);
#pragma unroll
                for (int j = 0; j < 4; j++)
                    wmma::load_matrix_sync(bf[j], Bs + (wno + j * 16) * BLDT + kk, BLDT);
#pragma unroll
                for (int i = 0; i < 4; i++)
#pragma unroll
                    for (int j = 0; j < 4; j++)
                        wmma::mma_sync(acc[i][j], af[i], bf[j], acc[i][j]);
            }
            __syncthreads();
        }

#pragma unroll
        for (int i = 0; i < 4; i++)
#pragma unroll
            for (int j = 0; j < 4; j++)
                wmma::store_matrix_sync(d_logits + (size_t)(m0 + wmo + i * 16) * LCOLS + n0 + wno + j * 16,
                                        acc[i][j], LCOLS, wmma::mem_row_major);
        __syncthreads();   // all smem reads done before next tile's prefetch overwrites
    }
}

// ============================ generic WMMA bf16 split GEMM (2-stage, LDT 40) ============================
template<int BM>
__global__ __launch_bounds__(256) void k_wgemm(
    const __nv_bfloat16* __restrict__ Ah, const __nv_bfloat16* __restrict__ Al, int lda,
    const __nv_bfloat16* __restrict__ Bh, const __nv_bfloat16* __restrict__ Bl, int ldb,
    const float* __restrict__ bias,
    const float* __restrict__ Dadd, int ldd,
    float* __restrict__ C, int ldc,
    int M, int N, int KP, int act)
{
    constexpr int MFR = (BM == 128) ? 2 : 1;
    constexpr int NFR = (BM == 128) ? 4 : 2;
    constexpr int AITEMS = BM * 4;
    constexpr int LDT = 40;
    constexpr int LDC_S = 136;
    constexpr int STAGE = (BM + 128) * LDT;

    extern __shared__ char smem[];
    __nv_bfloat16* tiles = (__nv_bfloat16*)smem;
    float* Cs = (float*)smem;

    const int tid = threadIdx.x, wid = tid >> 5;
    const int m0 = blockIdx.x * BM, n0 = blockIdx.y * 128;

    int wm, wn;
    if (BM == 128) { wm = wid & 3; wn = wid >> 2; }
    else           { wm = wid & 1; wn = wid >> 1; }
    const int wrow = wm * (16 * MFR);
    const int wcol = wn * (16 * NFR);

    wmma::fragment<wmma::accumulator, 16, 16, 16, float> acc[MFR][NFR];
#pragma unroll
    for (int i = 0; i < MFR; i++)
#pragma unroll
        for (int j = 0; j < NFR; j++)
            wmma::fill_fragment(acc[i][j], 0.0f);

    const int cpp = KP >> 5;
    const int total = 3 * cpp;

    auto prefetch = [&](int c, int stage) {
        int p = c / cpp;
        int kc = (c - p * cpp) << 5;
        const __nv_bfloat16* Ap = (p < 2) ? Ah : Al;
        const __nv_bfloat16* Bp = (p == 1) ? Bl : Bh;
        __nv_bfloat16* As = tiles + stage * STAGE;
        __nv_bfloat16* Bs = As + BM * LDT;
#pragma unroll
        for (int q = 0; q < (BM == 128 ? 2 : 1); q++) {
            int it = tid + q * 256;
            if (BM == 32 && it >= AITEMS) break;
            int r = it >> 2, seg = it & 3;
            int gm = m0 + r; if (gm >= M) gm = M - 1;
            cp_async16(smem_u32(As + r * LDT + seg * 8), Ap + (size_t)gm * lda + kc + seg * 8);
        }
#pragma unroll
        for (int q = 0; q < 2; q++) {
            int it = tid + q * 256;
            int r = it >> 2, seg = it & 3;
            int gn = n0 + r; if (gn >= N) gn = N - 1;
            cp_async16(smem_u32(Bs + r * LDT + seg * 8), Bp + (size_t)gn * ldb + kc + seg * 8);
        }
        cp_commit();
    };

    prefetch(0, 0);
    prefetch(1, 1);

    for (int c = 0; c < total; c++) {
        if (c + 1 < total) { asm volatile("cp.async.wait_group 1;\n" ::: "memory"); }
        else               { asm volatile("cp.async.wait_group 0;\n" ::: "memory"); }
        __syncthreads();
        const __nv_bfloat16* As = tiles + (c & 1) * STAGE;
        const __nv_bfloat16* Bs = As + BM * LDT;
#pragma unroll
        for (int kk = 0; kk < 32; kk += 16) {
            wmma::fragment<wmma::matrix_a, 16,16,16, __nv_bfloat16, wmma::row_major> af[MFR];
            wmma::fragment<wmma::matrix_b, 16,16,16, __nv_bfloat16, wmma::col_major> bf[NFR];
#pragma unroll
            for (int i = 0; i < MFR; i++)
                wmma::load_matrix_sync(af[i], As + (wrow + i * 16) * LDT + kk, LDT);
#pragma unroll
            for (int j = 0; j < NFR; j++)
                wmma::load_matrix_sync(bf[j], Bs + (wcol + j * 16) * LDT + kk, LDT);
#pragma unroll
            for (int i = 0; i < MFR; i++)
#pragma unroll
                for (int j = 0; j < NFR; j++)
                    wmma::mma_sync(acc[i][j], af[i], bf[j], acc[i][j]);
        }
        __syncthreads();
        if (c + 2 < total) prefetch(c + 2, c & 1);
    }

#pragma unroll
    for (int i = 0; i < MFR; i++)
#pragma unroll
        for (int j = 0; j < NFR; j++)
            wmma::store_matrix_sync(Cs + (wrow + i * 16) * LDC_S + wcol + j * 16,
                                    acc[i][j], LDC_S, wmma::mem_row_major);
    __syncthreads();
    for (int idx = tid; idx < BM * 128; idx += 256) {
        int r = idx >> 7, cc = idx & 127;
        int gm = m0 + r, gn = n0 + cc;
        if (gm < M && gn < N) {
            float v = Cs[r * LDC_S + cc];
            if (bias) v += bias[gn];
            if (Dadd) v += Dadd[(size_t)gm * ldd + gn];
            if (act)  v = tanhf(v);
            C[(size_t)gm * ldc + gn] = v;
        }
    }
}

// ============================ persistent recurrence kernel ============================
__global__ __launch_bounds__(256) void k_recur(const float* __restrict__ ann,
                                               const float* __restrict__ w_a,
                                               float* __restrict__ attns,
                                               float* __restrict__ hidden)
{
    __shared__ char smr[40192];
    const int bid = blockIdx.x;
    const int tid = threadIdx.x;
    const int wid = tid >> 5;

    __nv_bfloat16* Ath = (__nv_bfloat16*)smr;
    __nv_bfloat16* Atl = Ath + 2 * 32 * 40;
    __nv_bfloat16* Bth = Atl + 2 * 32 * 40;
    __nv_bfloat16* Btl = Bth + 2 * 64 * 40;
    float* Cs = (float*)(Btl + 2 * 64 * 40);
    float* sc  = (float*)smr;
    float* sat = (float*)smr;
    float* sgi = sat + 64;

    for (int step = 0; step < NSTEP; step++) {
        const int cur = step & 1;
        // ---- phase A: ghp = h @ [W_hh; W_c1]^T + bcomb ----
        if (bid < 63) {
            const int n0 = bid * 64;
            const int wm = wid & 1, wn = wid >> 1;
            const __nv_bfloat16* hH = d_hsH[cur];
            const __nv_bfloat16* hL = d_hsL[cur];
            wmma::fragment<wmma::accumulator, 16, 16, 16, float> acc;
            wmma::fill_fragment(acc, 0.0f);
#pragma unroll 1
            for (int c = 0; c < 32; c++) {
                const int st = c & 1;
                const int kc = c << 5;
                {
                    int it = tid & 127;
                    int r = it >> 2, seg = it & 3;
                    const __nv_bfloat16* src = (tid < 128) ? hH : hL;
                    __nv_bfloat16* dst = ((tid < 128) ? Ath : Atl) + st * (32 * 40);
                    *(uint4*)(dst + r * 40 + seg * 8) =
                        *(const uint4*)(src + (size_t)r * KP_H + kc + seg * 8);
                }
#pragma unroll
                for (int q = 0; q < 2; q++) {
                    int it = tid + q * 256;
                    int r = (it & 255) >> 2, seg = it & 3;
                    int gn = n0 + r; if (gn >= NGH) gn = NGH - 1;
                    const __nv_bfloat16* src = (it < 256) ? d_WhcH : d_WhcL;
                    __nv_bfloat16* dst = ((it < 256) ? Bth : Btl) + st * (64 * 40);
                    *(uint4*)(dst + r * 40 + seg * 8) =
                        *(const uint4*)(src + (size_t)gn * KP_H + kc + seg * 8);
                }
                __syncthreads();
#pragma unroll
                for (int kk = 0; kk < 32; kk += 16) {
                    wmma::fragment<wmma::matrix_a, 16,16,16, __nv_bfloat16, wmma::row_major> ah, al;
                    wmma::fragment<wmma::matrix_b, 16,16,16, __nv_bfloat16, wmma::col_major> bh, bl;
                    wmma::load_matrix_sync(ah, Ath + st * (32*40) + (wm * 16) * 40 + kk, 40);
                    wmma::load_matrix_sync(al, Atl + st * (32*40) + (wm * 16) * 40 + kk, 40);
                    wmma::load_matrix_sync(bh, Bth + st * (64*40) + (wn * 16) * 40 + kk, 40);
                    wmma::load_matrix_sync(bl, Btl + st * (64*40) + (wn * 16) * 40 + kk, 40);
                    wmma::mma_sync(acc, ah, bh, acc);
                    wmma::mma_sync(acc, ah, bl, acc);
                    wmma::mma_sync(acc, al, bh, acc);
                }
            }
            __syncthreads();
            wmma::store_matrix_sync(Cs + (wm * 16) * 72 + wn * 16, acc, 72, wmma::mem_row_major);
            __syncthreads();
            for (int idx = tid; idx < 32 * 64; idx += 256) {
                int r = idx >> 6, cc = idx & 63;
                int gn = n0 + cc;
                if (gn < NGH)
                    d_ghp[r * NGH + gn] = Cs[r * 72 + cc] + d_bcomb[gn];
            }
        }
        gridbar();

        // ---- phase B: attention + softmax over batch ----
        if (bid < SRC) {
            const int s = bid;
            int b = tid >> 3, jt = tid & 7;
            const float* hp = d_ghp + b * NGH + 3 * DCH;
            const float* ap = d_annProj + (size_t)(s * BSZ + b) * DCH;
            float acc = 0.f;
            for (int j = jt; j < DCH; j += 8)
                acc += tanhf(hp[j] + ap[j]) * w_a[j];
            for (int off = 4; off; off >>= 1)
                acc += __shfl_down_sync(0xffffffffu, acc, off, 8);
            if (jt == 0) sc[b] = acc;
            __syncthreads();
            if (tid < 32) {
                float v = sc[tid];
                float m = v;
                for (int off = 16; off; off >>= 1) m = fmaxf(m, __shfl_xor_sync(0xffffffffu, m, off));
                float e = expf(v - m);
                float ssum = e;
                for (int off = 16; off; off >>= 1) ssum += __shfl_xor_sync(0xffffffffu, ssum, off);
                float a = e / ssum;
                d_attnS[s * BSZ + tid] = a;
                attns[(size_t)(step + 1) * SRC * BSZ + s * BSZ + tid] = a;
            }
        }
        gridbar();

        // ---- phase C: context + gi + GRU gates ----
        if (bid < BSZ) {
            const int b = bid;
            if (tid < SRC) sat[tid] = d_attnS[tid * BSZ + b];
            __syncthreads();
            for (int e = tid; e < 2 * ECH; e += 256) {
                float acc = 0.f;
                const float* ap = ann + (size_t)b * (2 * ECH) + e;
#pragma unroll 10
                for (int s = 0; s < SRC; s++)
                    acc += sat[s] * ap[(size_t)s * BSZ * (2 * ECH)];
                d_C2[(size_t)(step * BSZ + b) * KP_WP + EMBED + DCH + e] = __float2half(acc);
            }
            const float* gE = d_giEmb + ((size_t)step * BSZ + b) * 3 * DCH;
            for (int j = tid; j < 3 * DCH; j += 256) {
                float acc = gE[j];
                const float* ip = d_annIh + (size_t)b * 3 * DCH + j;
#pragma unroll 10
                for (int s = 0; s < SRC; s++)
                    acc += sat[s] * ip[(size_t)s * BSZ * 3 * DCH];
                sgi[j] = acc;
            }
            __syncthreads();
            const float* gh = d_ghp + b * NGH;
            for (int j = tid; j < DCH; j += 256) {
                float r = 1.f / (1.f + expf(-(sgi[j] + gh[j])));
                float z = 1.f / (1.f + expf(-(sgi[DCH + j] + gh[DCH + j])));
                float n = tanhf(sgi[2 * DCH + j] + r * gh[2 * DCH + j]);
                float hp = d_hbuf[cur][b * DCH + j];
                float hn = (1.f - z) * n + z * hp;
                d_hbuf[cur ^ 1][b * DCH + j] = hn;
                __nv_bfloat16 hh = __float2bfloat16(hn);
                d_hsH[cur ^ 1][b * KP_H + j] = hh;
                d_hsL[cur ^ 1][b * KP_H + j] = __float2bfloat16(hn - __bfloat162float(hh));
                d_C2[(size_t)(step * BSZ + b) * KP_WP + EMBED + j] = __float2half(hp);
                if (step == NSTEP - 1) hidden[b * DCH + j] = hn;
            }
        }
        gridbar();
    }
}

// ============================ small kernels ============================
__global__ void k_split8(const float* __restrict__ src, int sld, int colOff, int rows, int cols,
                         __nv_bfloat16* __restrict__ hi, __nv_bfloat16* __restrict__ lo, int dld)
{
    int i8 = blockIdx.x * blockDim.x + threadIdx.x;
    int total8 = (rows * dld) >> 3;
    if (i8 >= total8) return;
    int i = i8 << 3;
    int r = i / dld, c = i - r * dld;
    float x[8];
    if (c + 7 < cols) {
        const float* p = src + (size_t)r * sld + colOff + c;
        *(float4*)(x)     = *(const float4*)(p);
        *(float4*)(x + 4) = *(const float4*)(p + 4);
    } else {
#pragma unroll
        for (int q = 0; q < 8; q++)
            x[q] = (c + q < cols) ? src[(size_t)r * sld + colOff + c + q] : 0.f;
    }
    __nv_bfloat16 h[8], l[8];
#pragma unroll
    for (int q = 0; q < 8; q++) {
        h[q] = __float2bfloat16(x[q]);
        l[q] = __float2bfloat16(x[q] - __bfloat162float(h[q]));
    }
    *(uint4*)(hi + i) = *(uint4*)h;
    *(uint4*)(lo + i) = *(uint4*)l;
}

// fp16 hi/lo split, 8 elems/thread (W_p)
__global__ void k_splitH8(const float* __restrict__ src, int sld, int colOff, int rows, int cols,
                          __half* __restrict__ hi, __half* __restrict__ lo, int dld)
{
    int i8 = blockIdx.x * blockDim.x + threadIdx.x;
    int total8 = (rows * dld) >> 3;
    if (i8 >= total8) return;
    int i = i8 << 3;
    int r = i / dld, c = i - r * dld;
    float x[8];
    if (c + 7 < cols) {
        const float* p = src + (size_t)r * sld + colOff + c;
        *(float4*)(x)     = *(const float4*)(p);
        *(float4*)(x + 4) = *(const float4*)(p + 4);
    } else {
#pragma unroll
        for (int q = 0; q < 8; q++)
            x[q] = (c + q < cols) ? src[(size_t)r * sld + colOff + c + q] : 0.f;
    }
    __half h[8], l[8];
#pragma unroll
    for (int q = 0; q < 8; q++) {
        h[q] = __float2half(x[q]);
        l[q] = __float2half(x[q] - __half2float(h[q]));
    }
    *(uint4*)(hi + i) = *(uint4*)h;
    *(uint4*)(lo + i) = *(uint4*)l;
}

__global__ void k_zero(float* __restrict__ preds0, float* __restrict__ attns0, int n)
{
    int i = blockIdx.x * blockDim.x + threadIdx.x;
    if (i < n) preds0[i] = 0.f;
    if (i < SRC * BSZ) attns0[i] = 0.f;
}

__global__ void k_bcomb(const float* __restrict__ b_hh)
{
    int i = blockIdx.x * blockDim.x + threadIdx.x;
    if (i < NGH) d_bcomb[i] = (i < 3 * DCH) ? b_hh[i] : 0.f;
}

__global__ void k_embedS(const int* __restrict__ tok, const float* __restrict__ emb)
{
    int i = blockIdx.x * blockDim.x + threadIdx.x;
    if (i >= MROWS * KP_EMB) return;
    int m = i / KP_EMB, e = i - m * KP_EMB;
    float x = (e < EMBED) ? emb[(size_t)tok[m] * EMBED + e] : 0.f;
    __nv_bfloat16 h = __float2bfloat16(x);
    d_EmbH[i] = h;
    d_EmbL[i] = __float2bfloat16(x - __bfloat162float(h));
    if (e < EMBED)
        d_C2[(size_t)m * KP_WP + e] = __float2half(x);
}

__global__ __launch_bounds__(256) void k_lsm(const float* __restrict__ bias, float* __restrict__ preds)
{
    int m = blockIdx.x;
    const float* row = d_logits + (size_t)m * LCOLS;
    float* outr = preds + (size_t)(m + BSZ) * VOCAB;
    int t = threadIdx.x;
    __shared__ float rm[256], rs[256];
    float mx = -1e30f, sum = 0.f;
    for (int v = t; v < VOCAB; v += 256) {
        float x = row[v] + bias[v];
        if (x > mx) { sum = sum * expf(mx - x) + 1.f; mx = x; }
        else sum += expf(x - mx);
    }
    rm[t] = mx; rs[t] = sum; __syncthreads();
    for (int s2 = 128; s2; s2 >>= 1) {
        if (t < s2) {
            float m1 = rm[t], m2 = rm[t + s2];
            float M = fmaxf(m1, m2);
            rs[t] = rs[t] * expf(m1 - M) + rs[t + s2] * expf(m2 - M);
            rm[t] = M;
        }
        __syncthreads();
    }
    float lse = rm[0] + logf(rs[0]);
    for (int v = t; v < VOCAB; v += 256)
        outr[v] = row[v] + bias[v] - lse;
}

// ============================ host ============================
#define SYM(p, s) do { void* _t; cudaGetSymbolAddress(&_t, s); p = (decltype(p))_t; } while (0)

#define SMEM_G128 (128 * 136 * 4)
#define SMEM_G32  (2 * (32 + 128) * 40 * 2 + 1024)

static inline void g128(const __nv_bfloat16* Ah, const __nv_bfloat16* Al, int lda,
                        const __nv_bfloat16* Bh, const __nv_bfloat16* Bl, int ldb,
                        const float* bias, const float* Dadd, int ldd,
                        float* C, int ldc, int M, int N, int KP, int act)
{
    dim3 g((M + 127) / 128, (N + 127) / 128);
    k_wgemm<128><<<g, 256, SMEM_G128>>>(Ah, Al, lda, Bh, Bl, ldb, bias, Dadd, ldd, C, ldc, M, N, KP, act);
}
static inline void g32(const __nv_bfloat16* Ah, const __nv_bfloat16* Al, int lda,
                       const __nv_bfloat16* Bh, const __nv_bfloat16* Bl, int ldb,
                       const float* bias, const float* Dadd, int ldd,
                       float* C, int ldc, int M, int N, int KP, int act)
{
    dim3 g((M + 31) / 32, (N + 127) / 128);
    k_wgemm<32><<<g, 256, SMEM_G32>>>(Ah, Al, lda, Bh, Bl, ldb, bias, Dadd, ldd, C, ldc, M, N, KP, act);
}

extern "C" void kernel_launch(void* const* d_in, const int* in_sizes, int n_in,
                              void* d_out, int out_size)
{
    (void)in_sizes; (void)n_in; (void)out_size;
    const int*   tok  = (const int*)  d_in[0];
    const float* ann  = (const float*)d_in[1];
    const float* emb  = (const float*)d_in[2];
    const float* W_h  = (const float*)d_in[3];
    const float* b_h  = (const float*)d_in[4];
    const float* W_c  = (const float*)d_in[5];
    const float* b_c  = (const float*)d_in[6];
    const float* w_a  = (const float*)d_in[7];
    const float* W_ih = (const float*)d_in[8];
    const float* W_hh = (const float*)d_in[9];
    const float* b_ih = (const float*)d_in[10];
    const float* b_hh = (const float*)d_in[11];
    const float* W_p  = (const float*)d_in[12];
    const float* b_p  = (const float*)d_in[13];

    float* out    = (float*)d_out;
    float* preds  = out;
    float* hidden = out + (size_t)TRGN * BSZ * VOCAB;
    float* attns  = hidden + BSZ * DCH;

    static bool attrDone = false;
    if (!attrDone) {
        cudaFuncSetAttribute(k_wgemm<128>, cudaFuncAttributeMaxDynamicSharedMemorySize, SMEM_G128);
        cudaFuncSetAttribute(k_wgemm<32>,  cudaFuncAttributeMaxDynamicSharedMemorySize, SMEM_G32);
        cudaFuncSetAttribute(k_wgemmBig,   cudaFuncAttributeMaxDynamicSharedMemorySize, SMEM_BIG);
        attrDone = true;
    }

    __half *WpH,*WpL;
    __nv_bfloat16 *annSH,*annSL,*WhcH,*WhcL,*Wc2H,*Wc2L;
    __nv_bfloat16 *Wih1H,*Wih1L,*Wih2H,*Wih2L,*WhH,*WhL,*EmbH,*EmbL,*a0H,*a0L,*hsH,*hsL;
    float *annProj,*annIh,*hbase,*giEmb;
    SYM(WpH, d_Wp16H); SYM(WpL, d_Wp16L);
    SYM(annSH, d_annSH); SYM(annSL, d_annSL);
    SYM(WhcH, d_WhcH); SYM(WhcL, d_WhcL);
    SYM(Wc2H, d_Wc2H); SYM(Wc2L, d_Wc2L);
    SYM(Wih1H, d_Wih1H); SYM(Wih1L, d_Wih1L);
    SYM(Wih2H, d_Wih2H); SYM(Wih2L, d_Wih2L);
    SYM(WhH, d_WhH);   SYM(WhL, d_WhL);
    SYM(EmbH, d_EmbH); SYM(EmbL, d_EmbL);
    SYM(a0H, d_a0H);   SYM(a0L, d_a0L);
    SYM(hsH, d_hsH);   SYM(hsL, d_hsL);
    SYM(annProj, d_annProj); SYM(annIh, d_annIh);
    SYM(hbase, d_hbuf); SYM(giEmb, d_giEmb);

    const int C2W = EMBED + DCH + 2 * ECH;   // 3620
    const int WIHW = EMBED + 2 * ECH;        // 2620

    auto split = [](const float* s, int sld, int off, int rows, int cols,
                    __nv_bfloat16* hi, __nv_bfloat16* lo, int dld) {
        long long tot8 = ((long long)rows * dld) >> 3;
        k_split8<<<(unsigned)((tot8 + 255) / 256), 256>>>(s, sld, off, rows, cols, hi, lo, dld);
    };
    // fp16 split of W_p
    {
        long long tot8 = ((long long)VOCAB * KP_WP) >> 3;
        k_splitH8<<<(unsigned)((tot8 + 255) / 256), 256>>>(W_p, C2W, 0, VOCAB, C2W, WpH, WpL, KP_WP);
    }
    split(W_hh, DCH, 0, 3 * DCH, DCH, WhcH, WhcL, KP_H);
    split(W_c, DCH + 2 * ECH, 0, DCH, DCH, WhcH + (size_t)3*DCH*KP_H,
          WhcL + (size_t)3*DCH*KP_H, KP_H);
    split(W_c, DCH + 2 * ECH, DCH, DCH, 2 * ECH, Wc2H, Wc2L, KP_CTX);
    split(W_ih, WIHW, 0,     3 * DCH, EMBED,   Wih1H, Wih1L, KP_EMB);
    split(W_ih, WIHW, EMBED, 3 * DCH, 2 * ECH, Wih2H, Wih2L, KP_CTX);
    split(W_h, ECH, 0, DCH, ECH, WhH, WhL, KP_H);
    split(ann, 2 * ECH, 0,   SRC * BSZ, 2 * ECH, annSH, annSL, KP_CTX);
    split(ann, 2 * ECH, ECH, BSZ, ECH, a0H, a0L, KP_H);
    k_bcomb<<<(NGH + 255) / 256, 256>>>(b_hh);
    k_zero<<<(BSZ * VOCAB + 255) / 256, 256>>>(preds, attns, BSZ * VOCAB);
    k_embedS<<<(MROWS * KP_EMB + 255) / 256, 256>>>(tok, emb);

    // h0 = tanh(ann0_bw @ W_h^T + b_h)
    g32(a0H, a0L, KP_H, WhH, WhL, KP_H, b_h, nullptr, 0, hbase, DCH, BSZ, DCH, KP_H, 1);
    split(hbase, DCH, 0, BSZ, DCH, hsH, hsL, KP_H);

    // annProj = ann @ W_c2^T + b_c
    g128(annSH, annSL, KP_CTX, Wc2H, Wc2L, KP_CTX, b_c, nullptr, 0,
         annProj, DCH, SRC * BSZ, DCH, KP_CTX, 0);
    // giEmb = embedded @ W_ih1^T + b_ih
    g128(EmbH, EmbL, KP_EMB, Wih1H, Wih1L, KP_EMB, b_ih, nullptr, 0,
         giEmb, 3 * DCH, MROWS, 3 * DCH, KP_EMB, 0);
    // annIh = ann @ W_ih2^T
    g128(annSH, annSL, KP_CTX, Wih2H, Wih2L, KP_CTX, nullptr, nullptr, 0,
         annIh, 3 * DCH, SRC * BSZ, 3 * DCH, KP_CTX, 0);

    // persistent 49-step recurrence (single launch)
    k_recur<<<RGRID, 256>>>(ann, w_a, attns, hidden);

    // big prediction GEMM (fp16, 2 products, persistent 148 CTAs) -> scratch, then bias+log_softmax -> preds
    k_wgemmBig<<<PGRID, 256, SMEM_BIG>>>();
    k_lsm<<<MROWS, 256>>>(b_p, preds);
}

// round 16
// speedup vs baseline: 1.9381x; 1.1739x over previous
#include <cuda_runtime.h>
#include <cuda_bf16.h>
#include <cuda_fp16.h>
#include <mma.h>
#include <math.h>
#include <stdint.h>

using namespace nvcuda;

#define SRC 50
#define TRGN 50
#define BSZ 32
#define EMBED 620
#define ECH 1000
#define DCH 1000
#define VOCAB 30000
#define NSTEP 49
#define MROWS (NSTEP*BSZ)          /* 1568 */
#define KP_WP 3648
#define KP_CTX 2048
#define KP_H 1024
#define KP_EMB 640
#define NGH 4000
#define RGRID 64
#define LROWS 1664
#define LCOLS 30208
#define MT 13
#define NT 118
#define NTILES (MT*NT)             /* 1534 */
#define PGRID 148

// ============================ static scratch (bss, zero-initialized) ============================
__device__ __half d_Wp16[(size_t)VOCAB*KP_WP];     // W_p fp16 (single)
__device__ __half d_C2[(size_t)MROWS*KP_WP];       // comb2, single fp16
__device__ __nv_bfloat16 d_annSH[(size_t)SRC*BSZ*KP_CTX], d_annSL[(size_t)SRC*BSZ*KP_CTX];
__device__ __nv_bfloat16 d_WhcH[(size_t)NGH*KP_H], d_WhcL[(size_t)NGH*KP_H];
__device__ __nv_bfloat16 d_Wc2H[(size_t)DCH*KP_CTX], d_Wc2L[(size_t)DCH*KP_CTX];
__device__ __nv_bfloat16 d_Wih1H[(size_t)3*DCH*KP_EMB], d_Wih1L[(size_t)3*DCH*KP_EMB];
__device__ __nv_bfloat16 d_Wih2H[(size_t)3*DCH*KP_CTX], d_Wih2L[(size_t)3*DCH*KP_CTX];
__device__ __nv_bfloat16 d_WhH[DCH*KP_H], d_WhL[DCH*KP_H];
__device__ __nv_bfloat16 d_EmbH[(size_t)MROWS*KP_EMB], d_EmbL[(size_t)MROWS*KP_EMB];
__device__ __nv_bfloat16 d_a0H[BSZ*KP_H], d_a0L[BSZ*KP_H];
__device__ __nv_bfloat16 d_hsH[2][BSZ*KP_H], d_hsL[2][BSZ*KP_H];
__device__ float d_annProj[SRC*BSZ*DCH];
__device__ float d_annIh[(size_t)SRC*BSZ*3*DCH];
__device__ float d_hbuf[2][BSZ*DCH];
__device__ float d_ghp[BSZ*NGH];
__device__ float d_attnS[SRC*BSZ];
__device__ float d_giEmb[(size_t)MROWS*3*DCH];
__device__ float d_bcomb[NGH];
__device__ float d_logits[(size_t)LROWS*LCOLS];

__device__ int g_cnt;
__device__ volatile int g_gen;

// ============================ helpers ============================
__device__ __forceinline__ uint32_t smem_u32(const void* p) {
    uint32_t a;
    asm("{ .reg .u64 t; cvta.to.shared.u64 t, %1; cvt.u32.u64 %0, t; }" : "=r"(a) : "l"(p));
    return a;
}
__device__ __forceinline__ void cp_async16(uint32_t dst, const void* src) {
    asm volatile("cp.async.cg.shared.global [%0], [%1], 16;\n" :: "r"(dst), "l"(src));
}
__device__ __forceinline__ void cp_commit() {
    asm volatile("cp.async.commit_group;\n" ::: "memory");
}
__device__ __forceinline__ void gridbar() {
    __syncthreads();
    if (threadIdx.x == 0) {
        __threadfence();
        int gen = g_gen;
        if (atomicAdd(&g_cnt, 1) == RGRID - 1) {
            g_cnt = 0;
            __threadfence();
            g_gen = gen + 1;
        } else {
            while (g_gen == gen) { __nanosleep(64); }
        }
        __threadfence();
    }
    __syncthreads();
}

// ============================ BIG GEMM: single fp16 product, persistent 148 CTAs, 128x256 tile, K64, 3-stage ============================
#define BLDT 72
#define BSTAGE ((128 + 256) * BLDT)
#define SMEM_BIG (3 * BSTAGE * 2)

__global__ __launch_bounds__(256, 1) void k_wgemmBig()
{
    extern __shared__ __half tiles[];
    const int tid = threadIdx.x, wid = tid >> 5;
    const int wm = wid & 1, wn = wid >> 1;
    const int wmo = wm * 64, wno = wn * 64;

    const int total = KP_WP >> 6;        // 57 chunks of K=64

    auto prefetch = [&](int m0, int n0, int c, int stage) {
        int kc = c << 6;
        __half* As = tiles + stage * BSTAGE;
        __half* Bs = As + 128 * BLDT;
#pragma unroll
        for (int q = 0; q < 4; q++) {          // A: 128 rows x 8 segs
            int it = tid + q * 256;
            int r = it >> 3, s = it & 7;
            int gm = m0 + r; if (gm >= MROWS) gm = MROWS - 1;
            cp_async16(smem_u32(As + r * BLDT + s * 8), d_C2 + (size_t)gm * KP_WP + kc + s * 8);
        }
#pragma unroll
        for (int q = 0; q < 8; q++) {          // B: 256 rows x 8 segs
            int it = tid + q * 256;
            int r = it >> 3, s = it & 7;
            int gn = n0 + r; if (gn >= VOCAB) gn = VOCAB - 1;
            cp_async16(smem_u32(Bs + r * BLDT + s * 8), d_Wp16 + (size_t)gn * KP_WP + kc + s * 8);
        }
        cp_commit();
    };

    for (int t = blockIdx.x; t < NTILES; t += PGRID) {
        const int m0 = (t % MT) * 128;
        const int n0 = (t / MT) * 256;

        wmma::fragment<wmma::accumulator, 16, 16, 16, float> acc[4][4];
#pragma unroll
        for (int i = 0; i < 4; i++)
#pragma unroll
            for (int j = 0; j < 4; j++) wmma::fill_fragment(acc[i][j], 0.0f);

        prefetch(m0, n0, 0, 0);
        prefetch(m0, n0, 1, 1);

        for (int c = 0; c < total; c++) {
            if (c + 1 < total) { asm volatile("cp.async.wait_group 1;\n" ::: "memory"); }
            else               { asm volatile("cp.async.wait_group 0;\n" ::: "memory"); }
            __syncthreads();
            if (c + 2 < total) prefetch(m0, n0, c + 2, (c + 2) % 3);
            const __half* As = tiles + (c % 3) * BSTAGE;
            const __half* Bs = As + 128 * BLDT;
#pragma unroll
            for (int kk = 0; kk < 64; kk += 16) {
                wmma::fragment<wmma::matrix_a, 16,16,16, __half, wmma::row_major> af[4];
                wmma::fragment<wmma::matrix_b, 16,16,16, __half, wmma::col_major> bf[4];
#pragma unroll
                for (int i = 0; i < 4; i++)
                    wmma::load_matrix_sync(af[i], As + (wmo + i * 16) * BLDT + kk, BLDT);
#pragma unroll
                for (int j = 0; j < 4; j++)
                    wmma::load_matrix_sync(bf[j], Bs + (wno + j * 16) * BLDT + kk, BLDT);
#pragma unroll
                for (int i = 0; i < 4; i++)
#pragma unroll
                    for (int j = 0; j < 4; j++)
                        wmma::mma_sync(acc[i][j], af[i], bf[j], acc[i][j]);
            }
            __syncthreads();
        }

#pragma unroll
        for (int i = 0; i < 4; i++)
#pragma unroll
            for (int j = 0; j < 4; j++)
                wmma::store_matrix_sync(d_logits + (size_t)(m0 + wmo + i * 16) * LCOLS + n0 + wno + j * 16,
                                        acc[i][j], LCOLS, wmma::mem_row_major);
        __syncthreads();
    }
}

// ============================ generic WMMA bf16 split GEMM (2-stage, LDT 40) ============================
template<int BM>
__global__ __launch_bounds__(256) void k_wgemm(
    const __nv_bfloat16* __restrict__ Ah, const __nv_bfloat16* __restrict__ Al, int lda,
    const __nv_bfloat16* __restrict__ Bh, const __nv_bfloat16* __restrict__ Bl, int ldb,
    const float* __restrict__ bias,
    const float* __restrict__ Dadd, int ldd,
    float* __restrict__ C, int ldc,
    int M, int N, int KP, int act)
{
    constexpr int MFR = (BM == 128) ? 2 : 1;
    constexpr int NFR = (BM == 128) ? 4 : 2;
    constexpr int AITEMS = BM * 4;
    constexpr int LDT = 40;
    constexpr int LDC_S = 136;
    constexpr int STAGE = (BM + 128) * LDT;

    extern __shared__ char smem[];
    __nv_bfloat16* tiles = (__nv_bfloat16*)smem;
    float* Cs = (float*)smem;

    const int tid = threadIdx.x, wid = tid >> 5;
    const int m0 = blockIdx.x * BM, n0 = blockIdx.y * 128;

    int wm, wn;
    if (BM == 128) { wm = wid & 3; wn = wid >> 2; }
    else           { wm = wid & 1; wn = wid >> 1; }
    const int wrow = wm * (16 * MFR);
    const int wcol = wn * (16 * NFR);

    wmma::fragment<wmma::accumulator, 16, 16, 16, float> acc[MFR][NFR];
#pragma unroll
    for (int i = 0; i < MFR; i++)
#pragma unroll
        for (int j = 0; j < NFR; j++)
            wmma::fill_fragment(acc[i][j], 0.0f);

    const int cpp = KP >> 5;
    const int total = 3 * cpp;

    auto prefetch = [&](int c, int stage) {
        int p = c / cpp;
        int kc = (c - p * cpp) << 5;
        const __nv_bfloat16* Ap = (p < 2) ? Ah : Al;
        const __nv_bfloat16* Bp = (p == 1) ? Bl : Bh;
        __nv_bfloat16* As = tiles + stage * STAGE;
        __nv_bfloat16* Bs = As + BM * LDT;
#pragma unroll
        for (int q = 0; q < (BM == 128 ? 2 : 1); q++) {
            int it = tid + q * 256;
            if (BM == 32 && it >= AITEMS) break;
            int r = it >> 2, seg = it & 3;
            int gm = m0 + r; if (gm >= M) gm = M - 1;
            cp_async16(smem_u32(As + r * LDT + seg * 8), Ap + (size_t)gm * lda + kc + seg * 8);
        }
#pragma unroll
        for (int q = 0; q < 2; q++) {
            int it = tid + q * 256;
            int r = it >> 2, seg = it & 3;
            int gn = n0 + r; if (gn >= N) gn = N - 1;
            cp_async16(smem_u32(Bs + r * LDT + seg * 8), Bp + (size_t)gn * ldb + kc + seg * 8);
        }
        cp_commit();
    };

    prefetch(0, 0);
    prefetch(1, 1);

    for (int c = 0; c < total; c++) {
        if (c + 1 < total) { asm volatile("cp.async.wait_group 1;\n" ::: "memory"); }
        else               { asm volatile("cp.async.wait_group 0;\n" ::: "memory"); }
        __syncthreads();
        const __nv_bfloat16* As = tiles + (c & 1) * STAGE;
        const __nv_bfloat16* Bs = As + BM * LDT;
#pragma unroll
        for (int kk = 0; kk < 32; kk += 16) {
            wmma::fragment<wmma::matrix_a, 16,16,16, __nv_bfloat16, wmma::row_major> af[MFR];
            wmma::fragment<wmma::matrix_b, 16,16,16, __nv_bfloat16, wmma::col_major> bf[NFR];
#pragma unroll
            for (int i = 0; i < MFR; i++)
                wmma::load_matrix_sync(af[i], As + (wrow + i * 16) * LDT + kk, LDT);
#pragma unroll
            for (int j = 0; j < NFR; j++)
                wmma::load_matrix_sync(bf[j], Bs + (wcol + j * 16) * LDT + kk, LDT);
#pragma unroll
            for (int i = 0; i < MFR; i++)
#pragma unroll
                for (int j = 0; j < NFR; j++)
                    wmma::mma_sync(acc[i][j], af[i], bf[j], acc[i][j]);
        }
        __syncthreads();
        if (c + 2 < total) prefetch(c + 2, c & 1);
    }

#pragma unroll
    for (int i = 0; i < MFR; i++)
#pragma unroll
        for (int j = 0; j < NFR; j++)
            wmma::store_matrix_sync(Cs + (wrow + i * 16) * LDC_S + wcol + j * 16,
                                    acc[i][j], LDC_S, wmma::mem_row_major);
    __syncthreads();
    for (int idx = tid; idx < BM * 128; idx += 256) {
        int r = idx >> 7, cc = idx & 127;
        int gm = m0 + r, gn = n0 + cc;
        if (gm < M && gn < N) {
            float v = Cs[r * LDC_S + cc];
            if (bias) v += bias[gn];
            if (Dadd) v += Dadd[(size_t)gm * ldd + gn];
            if (act)  v = tanhf(v);
            C[(size_t)gm * ldc + gn] = v;
        }
    }
}

// ============================ persistent recurrence kernel ============================
__global__ __launch_bounds__(256) void k_recur(const float* __restrict__ ann,
                                               const float* __restrict__ w_a,
                                               float* __restrict__ attns,
                                               float* __restrict__ hidden)
{
    __shared__ char smr[40192];
    const int bid = blockIdx.x;
    const int tid = threadIdx.x;
    const int wid = tid >> 5;

    __nv_bfloat16* Ath = (__nv_bfloat16*)smr;
    __nv_bfloat16* Atl = Ath + 2 * 32 * 40;
    __nv_bfloat16* Bth = Atl + 2 * 32 * 40;
    __nv_bfloat16* Btl = Bth + 2 * 64 * 40;
    float* Cs = (float*)(Btl + 2 * 64 * 40);
    float* sc  = (float*)smr;
    float* sat = (float*)smr;
    float* sgi = sat + 64;

    for (int step = 0; step < NSTEP; step++) {
        const int cur = step & 1;
        // ---- phase A: ghp = h @ [W_hh; W_c1]^T + bcomb ----
        if (bid < 63) {
            const int n0 = bid * 64;
            const int wm = wid & 1, wn = wid >> 1;
            const __nv_bfloat16* hH = d_hsH[cur];
            const __nv_bfloat16* hL = d_hsL[cur];
            wmma::fragment<wmma::accumulator, 16, 16, 16, float> acc;
            wmma::fill_fragment(acc, 0.0f);
#pragma unroll 1
            for (int c = 0; c < 32; c++) {
                const int st = c & 1;
                const int kc = c << 5;
                {
                    int it = tid & 127;
                    int r = it >> 2, seg = it & 3;
                    const __nv_bfloat16* src = (tid < 128) ? hH : hL;
                    __nv_bfloat16* dst = ((tid < 128) ? Ath : Atl) + st * (32 * 40);
                    *(uint4*)(dst + r * 40 + seg * 8) =
                        *(const uint4*)(src + (size_t)r * KP_H + kc + seg * 8);
                }
#pragma unroll
                for (int q = 0; q < 2; q++) {
                    int it = tid + q * 256;
                    int r = (it & 255) >> 2, seg = it & 3;
                    int gn = n0 + r; if (gn >= NGH) gn = NGH - 1;
                    const __nv_bfloat16* src = (it < 256) ? d_WhcH : d_WhcL;
                    __nv_bfloat16* dst = ((it < 256) ? Bth : Btl) + st * (64 * 40);
                    *(uint4*)(dst + r * 40 + seg * 8) =
                        *(const uint4*)(src + (size_t)gn * KP_H + kc + seg * 8);
                }
                __syncthreads();
#pragma unroll
                for (int kk = 0; kk < 32; kk += 16) {
                    wmma::fragment<wmma::matrix_a, 16,16,16, __nv_bfloat16, wmma::row_major> ah, al;
                    wmma::fragment<wmma::matrix_b, 16,16,16, __nv_bfloat16, wmma::col_major> bh, bl;
                    wmma::load_matrix_sync(ah, Ath + st * (32*40) + (wm * 16) * 40 + kk, 40);
                    wmma::load_matrix_sync(al, Atl + st * (32*40) + (wm * 16) * 40 + kk, 40);
                    wmma::load_matrix_sync(bh, Bth + st * (64*40) + (wn * 16) * 40 + kk, 40);
                    wmma::load_matrix_sync(bl, Btl + st * (64*40) + (wn * 16) * 40 + kk, 40);
                    wmma::mma_sync(acc, ah, bh, acc);
                    wmma::mma_sync(acc, ah, bl, acc);
                    wmma::mma_sync(acc, al, bh, acc);
                }
            }
            __syncthreads();
            wmma::store_matrix_sync(Cs + (wm * 16) * 72 + wn * 16, acc, 72, wmma::mem_row_major);
            __syncthreads();
            for (int idx = tid; idx < 32 * 64; idx += 256) {
                int r = idx >> 6, cc = idx & 63;
                int gn = n0 + cc;
                if (gn < NGH)
                    d_ghp[r * NGH + gn] = Cs[r * 72 + cc] + d_bcomb[gn];
            }
        }
        gridbar();

        // ---- phase B: attention + softmax over batch ----
        if (bid < SRC) {
            const int s = bid;
            int b = tid >> 3, jt = tid & 7;
            const float* hp = d_ghp + b * NGH + 3 * DCH;
            const float* ap = d_annProj + (size_t)(s * BSZ + b) * DCH;
            float acc = 0.f;
            for (int j = jt; j < DCH; j += 8)
                acc += tanhf(hp[j] + ap[j]) * w_a[j];
            for (int off = 4; off; off >>= 1)
                acc += __shfl_down_sync(0xffffffffu, acc, off, 8);
            if (jt == 0) sc[b] = acc;
            __syncthreads();
            if (tid < 32) {
                float v = sc[tid];
                float m = v;
                for (int off = 16; off; off >>= 1) m = fmaxf(m, __shfl_xor_sync(0xffffffffu, m, off));
                float e = expf(v - m);
                float ssum = e;
                for (int off = 16; off; off >>= 1) ssum += __shfl_xor_sync(0xffffffffu, ssum, off);
                float a = e / ssum;
                d_attnS[s * BSZ + tid] = a;
                attns[(size_t)(step + 1) * SRC * BSZ + s * BSZ + tid] = a;
            }
        }
        gridbar();

        // ---- phase C: context + gi + GRU gates ----
        if (bid < BSZ) {
            const int b = bid;
            if (tid < SRC) sat[tid] = d_attnS[tid * BSZ + b];
            __syncthreads();
            for (int e = tid; e < 2 * ECH; e += 256) {
                float acc = 0.f;
                const float* ap = ann + (size_t)b * (2 * ECH) + e;
#pragma unroll 10
                for (int s = 0; s < SRC; s++)
                    acc += sat[s] * ap[(size_t)s * BSZ * (2 * ECH)];
                d_C2[(size_t)(step * BSZ + b) * KP_WP + EMBED + DCH + e] = __float2half(acc);
            }
            const float* gE = d_giEmb + ((size_t)step * BSZ + b) * 3 * DCH;
            for (int j = tid; j < 3 * DCH; j += 256) {
                float acc = gE[j];
                const float* ip = d_annIh + (size_t)b * 3 * DCH + j;
#pragma unroll 10
                for (int s = 0; s < SRC; s++)
                    acc += sat[s] * ip[(size_t)s * BSZ * 3 * DCH];
                sgi[j] = acc;
            }
            __syncthreads();
            const float* gh = d_ghp + b * NGH;
            for (int j = tid; j < DCH; j += 256) {
                float r = 1.f / (1.f + expf(-(sgi[j] + gh[j])));
                float z = 1.f / (1.f + expf(-(sgi[DCH + j] + gh[DCH + j])));
                float n = tanhf(sgi[2 * DCH + j] + r * gh[2 * DCH + j]);
                float hp = d_hbuf[cur][b * DCH + j];
                float hn = (1.f - z) * n + z * hp;
                d_hbuf[cur ^ 1][b * DCH + j] = hn;
                __nv_bfloat16 hh = __float2bfloat16(hn);
                d_hsH[cur ^ 1][b * KP_H + j] = hh;
                d_hsL[cur ^ 1][b * KP_H + j] = __float2bfloat16(hn - __bfloat162float(hh));
                d_C2[(size_t)(step * BSZ + b) * KP_WP + EMBED + j] = __float2half(hp);
                if (step == NSTEP - 1) hidden[b * DCH + j] = hn;
            }
        }
        gridbar();
    }
}

// ============================ small kernels ============================
__global__ void k_split8(const float* __restrict__ src, int sld, int colOff, int rows, int cols,
                         __nv_bfloat16* __restrict__ hi, __nv_bfloat16* __restrict__ lo, int dld)
{
    int i8 = blockIdx.x * blockDim.x + threadIdx.x;
    int total8 = (rows * dld) >> 3;
    if (i8 >= total8) return;
    int i = i8 << 3;
    int r = i / dld, c = i - r * dld;
    float x[8];
    if (c + 7 < cols) {
        const float* p = src + (size_t)r * sld + colOff + c;
        *(float4*)(x)     = *(const float4*)(p);
        *(float4*)(x + 4) = *(const float4*)(p + 4);
    } else {
#pragma unroll
        for (int q = 0; q < 8; q++)
            x[q] = (c + q < cols) ? src[(size_t)r * sld + colOff + c + q] : 0.f;
    }
    __nv_bfloat16 h[8], l[8];
#pragma unroll
    for (int q = 0; q < 8; q++) {
        h[q] = __float2bfloat16(x[q]);
        l[q] = __float2bfloat16(x[q] - __bfloat162float(h[q]));
    }
    *(uint4*)(hi + i) = *(uint4*)h;
    *(uint4*)(lo + i) = *(uint4*)l;
}

// fp32 -> fp16 convert (single), 8 elems/thread
__global__ void k_cvtH8(const float* __restrict__ src, int sld, int rows, int cols,
                        __half* __restrict__ dst, int dld)
{
    int i8 = blockIdx.x * blockDim.x + threadIdx.x;
    int total8 = (rows * dld) >> 3;
    if (i8 >= total8) return;
    int i = i8 << 3;
    int r = i / dld, c = i - r * dld;
    float x[8];
    if (c + 7 < cols) {
        const float* p = src + (size_t)r * sld + c;
        *(float4*)(x)     = *(const float4*)(p);
        *(float4*)(x + 4) = *(const float4*)(p + 4);
    } else {
#pragma unroll
        for (int q = 0; q < 8; q++)
            x[q] = (c + q < cols) ? src[(size_t)r * sld + c + q] : 0.f;
    }
    __half h[8];
#pragma unroll
    for (int q = 0; q < 8; q++) h[q] = __float2half(x[q]);
    *(uint4*)(dst + i) = *(uint4*)h;
}

__global__ void k_zero(float* __restrict__ preds0, float* __restrict__ attns0, int n)
{
    int i = blockIdx.x * blockDim.x + threadIdx.x;
    if (i < n) preds0[i] = 0.f;
    if (i < SRC * BSZ) attns0[i] = 0.f;
}

__global__ void k_bcomb(const float* __restrict__ b_hh)
{
    int i = blockIdx.x * blockDim.x + threadIdx.x;
    if (i < NGH) d_bcomb[i] = (i < 3 * DCH) ? b_hh[i] : 0.f;
}

__global__ void k_embedS(const int* __restrict__ tok, const float* __restrict__ emb)
{
    int i = blockIdx.x * blockDim.x + threadIdx.x;
    if (i >= MROWS * KP_EMB) return;
    int m = i / KP_EMB, e = i - m * KP_EMB;
    float x = (e < EMBED) ? emb[(size_t)tok[m] * EMBED + e] : 0.f;
    __nv_bfloat16 h = __float2bfloat16(x);
    d_EmbH[i] = h;
    d_EmbL[i] = __float2bfloat16(x - __bfloat162float(h));
    if (e < EMBED)
        d_C2[(size_t)m * KP_WP + e] = __float2half(x);
}

__global__ __launch_bounds__(256) void k_lsm(const float* __restrict__ bias, float* __restrict__ preds)
{
    int m = blockIdx.x;
    const float* row = d_logits + (size_t)m * LCOLS;
    float* outr = preds + (size_t)(m + BSZ) * VOCAB;
    int t = threadIdx.x;
    __shared__ float rm[256], rs[256];
    float mx = -1e30f, sum = 0.f;
    for (int v = t; v < VOCAB; v += 256) {
        float x = row[v] + bias[v];
        if (x > mx) { sum = sum * expf(mx - x) + 1.f; mx = x; }
        else sum += expf(x - mx);
    }
    rm[t] = mx; rs[t] = sum; __syncthreads();
    for (int s2 = 128; s2; s2 >>= 1) {
        if (t < s2) {
            float m1 = rm[t], m2 = rm[t + s2];
            float M = fmaxf(m1, m2);
            rs[t] = rs[t] * expf(m1 - M) + rs[t + s2] * expf(m2 - M);
            rm[t] = M;
        }
        __syncthreads();
    }
    float lse = rm[0] + logf(rs[0]);
    for (int v = t; v < VOCAB; v += 256)
        outr[v] = row[v] + bias[v] - lse;
}

// ============================ host ============================
#define SYM(p, s) do { void* _t; cudaGetSymbolAddress(&_t, s); p = (decltype(p))_t; } while (0)

#define SMEM_G128 (128 * 136 * 4)
#define SMEM_G32  (2 * (32 + 128) * 40 * 2 + 1024)

static inline void g128(const __nv_bfloat16* Ah, const __nv_bfloat16* Al, int lda,
                        const __nv_bfloat16* Bh, const __nv_bfloat16* Bl, int ldb,
                        const float* bias, const float* Dadd, int ldd,
                        float* C, int ldc, int M, int N, int KP, int act)
{
    dim3 g((M + 127) / 128, (N + 127) / 128);
    k_wgemm<128><<<g, 256, SMEM_G128>>>(Ah, Al, lda, Bh, Bl, ldb, bias, Dadd, ldd, C, ldc, M, N, KP, act);
}
static inline void g32(const __nv_bfloat16* Ah, const __nv_bfloat16* Al, int lda,
                       const __nv_bfloat16* Bh, const __nv_bfloat16* Bl, int ldb,
                       const float* bias, const float* Dadd, int ldd,
                       float* C, int ldc, int M, int N, int KP, int act)
{
    dim3 g((M + 31) / 32, (N + 127) / 128);
    k_wgemm<32><<<g, 256, SMEM_G32>>>(Ah, Al, lda, Bh, Bl, ldb, bias, Dadd, ldd, C, ldc, M, N, KP, act);
}

extern "C" void kernel_launch(void* const* d_in, const int* in_sizes, int n_in,
                              void* d_out, int out_size)
{
    (void)in_sizes; (void)n_in; (void)out_size;
    const int*   tok  = (const int*)  d_in[0];
    const float* ann  = (const float*)d_in[1];
    const float* emb  = (const float*)d_in[2];
    const float* W_h  = (const float*)d_in[3];
    const float* b_h  = (const float*)d_in[4];
    const float* W_c  = (const float*)d_in[5];
    const float* b_c  = (const float*)d_in[6];
    const float* w_a  = (const float*)d_in[7];
    const float* W_ih = (const float*)d_in[8];
    const float* W_hh = (const float*)d_in[9];
    const float* b_ih = (const float*)d_in[10];
    const float* b_hh = (const float*)d_in[11];
    const float* W_p  = (const float*)d_in[12];
    const float* b_p  = (const float*)d_in[13];

    float* out    = (float*)d_out;
    float* preds  = out;
    float* hidden = out + (size_t)TRGN * BSZ * VOCAB;
    float* attns  = hidden + BSZ * DCH;

    static bool attrDone = false;
    if (!attrDone) {
        cudaFuncSetAttribute(k_wgemm<128>, cudaFuncAttributeMaxDynamicSharedMemorySize, SMEM_G128);
        cudaFuncSetAttribute(k_wgemm<32>,  cudaFuncAttributeMaxDynamicSharedMemorySize, SMEM_G32);
        cudaFuncSetAttribute(k_wgemmBig,   cudaFuncAttributeMaxDynamicSharedMemorySize, SMEM_BIG);
        attrDone = true;
    }

    __half *Wp16;
    __nv_bfloat16 *annSH,*annSL,*WhcH,*WhcL,*Wc2H,*Wc2L;
    __nv_bfloat16 *Wih1H,*Wih1L,*Wih2H,*Wih2L,*WhH,*WhL,*EmbH,*EmbL,*a0H,*a0L,*hsH,*hsL;
    float *annProj,*annIh,*hbase,*giEmb;
    SYM(Wp16, d_Wp16);
    SYM(annSH, d_annSH); SYM(annSL, d_annSL);
    SYM(WhcH, d_WhcH); SYM(WhcL, d_WhcL);
    SYM(Wc2H, d_Wc2H); SYM(Wc2L, d_Wc2L);
    SYM(Wih1H, d_Wih1H); SYM(Wih1L, d_Wih1L);
    SYM(Wih2H, d_Wih2H); SYM(Wih2L, d_Wih2L);
    SYM(WhH, d_WhH);   SYM(WhL, d_WhL);
    SYM(EmbH, d_EmbH); SYM(EmbL, d_EmbL);
    SYM(a0H, d_a0H);   SYM(a0L, d_a0L);
    SYM(hsH, d_hsH);   SYM(hsL, d_hsL);
    SYM(annProj, d_annProj); SYM(annIh, d_annIh);
    SYM(hbase, d_hbuf); SYM(giEmb, d_giEmb);

    const int C2W = EMBED + DCH + 2 * ECH;   // 3620
    const int WIHW = EMBED + 2 * ECH;        // 2620

    auto split = [](const float* s, int sld, int off, int rows, int cols,
                    __nv_bfloat16* hi, __nv_bfloat16* lo, int dld) {
        long long tot8 = ((long long)rows * dld) >> 3;
        k_split8<<<(unsigned)((tot8 + 255) / 256), 256>>>(s, sld, off, rows, cols, hi, lo, dld);
    };
    // fp16 convert of W_p (single product)
    {
        long long tot8 = ((long long)VOCAB * KP_WP) >> 3;
        k_cvtH8<<<(unsigned)((tot8 + 255) / 256), 256>>>(W_p, C2W, VOCAB, C2W, Wp16, KP_WP);
    }
    split(W_hh, DCH, 0, 3 * DCH, DCH, WhcH, WhcL, KP_H);
    split(W_c, DCH + 2 * ECH, 0, DCH, DCH, WhcH + (size_t)3*DCH*KP_H,
          WhcL + (size_t)3*DCH*KP_H, KP_H);
    split(W_c, DCH + 2 * ECH, DCH, DCH, 2 * ECH, Wc2H, Wc2L, KP_CTX);
    split(W_ih, WIHW, 0,     3 * DCH, EMBED,   Wih1H, Wih1L, KP_EMB);
    split(W_ih, WIHW, EMBED, 3 * DCH, 2 * ECH, Wih2H, Wih2L, KP_CTX);
    split(W_h, ECH, 0, DCH, ECH, WhH, WhL, KP_H);
    split(ann, 2 * ECH, 0,   SRC * BSZ, 2 * ECH, annSH, annSL, KP_CTX);
    split(ann, 2 * ECH, ECH, BSZ, ECH, a0H, a0L, KP_H);
    k_bcomb<<<(NGH + 255) / 256, 256>>>(b_hh);
    k_zero<<<(BSZ * VOCAB + 255) / 256, 256>>>(preds, attns, BSZ * VOCAB);
    k_embedS<<<(MROWS * KP_EMB + 255) / 256, 256>>>(tok, emb);

    // h0 = tanh(ann0_bw @ W_h^T + b_h)
    g32(a0H, a0L, KP_H, WhH, WhL, KP_H, b_h, nullptr, 0, hbase, DCH, BSZ, DCH, KP_H, 1);
    split(hbase, DCH, 0, BSZ, DCH, hsH, hsL, KP_H);

    // annProj = ann @ W_c2^T + b_c
    g128(annSH, annSL, KP_CTX, Wc2H, Wc2L, KP_CTX, b_c, nullptr, 0,
         annProj, DCH, SRC * BSZ, DCH, KP_CTX, 0);
    // giEmb = embedded @ W_ih1^T + b_ih
    g128(EmbH, EmbL, KP_EMB, Wih1H, Wih1L, KP_EMB, b_ih, nullptr, 0,
         giEmb, 3 * DCH, MROWS, 3 * DCH, KP_EMB, 0);
    // annIh = ann @ W_ih2^T
    g128(annSH, annSL, KP_CTX, Wih2H, Wih2L, KP_CTX, nullptr, nullptr, 0,
         annIh, 3 * DCH, SRC * BSZ, 3 * DCH, KP_CTX, 0);

    // persistent 49-step recurrence (single launch)
    k_recur<<<RGRID, 256>>>(ann, w_a, attns, hidden);

    // big prediction GEMM (single fp16 product, persistent 148 CTAs) -> scratch, then bias+log_softmax -> preds
    k_wgemmBig<<<PGRID, 256, SMEM_BIG>>>();
    k_lsm<<<MROWS, 256>>>(b_p, preds);
}